// round 12
// baseline (speedup 1.0000x reference)
#include <cuda_runtime.h>
#include <cuda_bf16.h>
#include <cstdint>
#include <cstddef>

#define BB 2
#define TT 2048
#define DD 1024
#define HH 16
#define HD 64
#define MM (BB*TT)
#define NSM 148

// ---------------- packed, pre-swizzled scratch (allocation-free) ----------------
__device__ __nv_bfloat16 g_xp_hi[(size_t)MM * DD];
__device__ __nv_bfloat16 g_xp_lo[(size_t)MM * DD];
__device__ __nv_bfloat16 g_wqkvp_hi[(size_t)3 * DD * DD];
__device__ __nv_bfloat16 g_wqkvp_lo[(size_t)3 * DD * DD];
__device__ __nv_bfloat16 g_woutp_hi[(size_t)DD * DD];
__device__ __nv_bfloat16 g_woutp_lo[(size_t)DD * DD];
__device__ __nv_bfloat16 g_qkvp_hi[(size_t)3 * MM * DD];
__device__ __nv_bfloat16 g_qkvp_lo[(size_t)3 * MM * DD];
__device__ __nv_bfloat16 g_yp_hi[(size_t)MM * DD];
__device__ __nv_bfloat16 g_yp_lo[(size_t)MM * DD];
__device__ int g_mask_flag = 1;
__device__ int g_ctrs[4];          // persistent-kernel tile counters

// ---------------- base-target PTX helpers ----------------
__device__ __forceinline__ uint32_t smem_u32(const void* p) {
    uint32_t a;
    asm("{ .reg .u64 t; cvta.to.shared.u64 t, %1; cvt.u32.u64 %0, t; }"
        : "=r"(a) : "l"(p));
    return a;
}
__device__ __forceinline__ void mbar_init(uint32_t mbar, uint32_t cnt) {
    asm volatile("mbarrier.init.shared.b64 [%0], %1;" :: "r"(mbar), "r"(cnt) : "memory");
}
__device__ __forceinline__ void mbar_expect_tx(uint32_t mbar, uint32_t bytes) {
    asm volatile("mbarrier.arrive.expect_tx.shared.b64 _, [%0], %1;"
                 :: "r"(mbar), "r"(bytes) : "memory");
}
__device__ __forceinline__ void mbar_wait(uint32_t mbar, uint32_t parity) {
    asm volatile(
        "{\n\t.reg .pred P;\n\t"
        "WL_%=:\n\t"
        "mbarrier.try_wait.parity.acquire.cta.shared::cta.b64 P, [%0], %1, 0x989680;\n\t"
        "@P bra WD_%=;\n\t"
        "bra WL_%=;\n\t"
        "WD_%=:\n\t}"
        :: "r"(mbar), "r"(parity) : "memory");
}
__device__ __forceinline__ void bulk_g2s(uint32_t dst, const void* src,
                                         uint32_t bytes, uint32_t mbar) {
    asm volatile(
        "cp.async.bulk.shared::cluster.global.mbarrier::complete_tx::bytes "
        "[%0], [%1], %2, [%3];"
        :: "r"(dst), "l"(src), "r"(bytes), "r"(mbar) : "memory");
}
__device__ __forceinline__ void ldsm_x4(uint32_t addr, uint32_t r[4]) {
    asm volatile("ldmatrix.sync.aligned.m8n8.x4.shared.b16 {%0,%1,%2,%3}, [%4];"
                 : "=r"(r[0]), "=r"(r[1]), "=r"(r[2]), "=r"(r[3]) : "r"(addr));
}
__device__ __forceinline__ void ldsm_x4_t(uint32_t addr, uint32_t r[4]) {
    asm volatile("ldmatrix.sync.aligned.m8n8.x4.trans.shared.b16 {%0,%1,%2,%3}, [%4];"
                 : "=r"(r[0]), "=r"(r[1]), "=r"(r[2]), "=r"(r[3]) : "r"(addr));
}
__device__ __forceinline__ void mma_bf16(float d[4], const uint32_t a[4],
                                         uint32_t b0, uint32_t b1) {
    asm volatile(
        "mma.sync.aligned.m16n8k16.row.col.f32.bf16.bf16.f32 "
        "{%0,%1,%2,%3}, {%4,%5,%6,%7}, {%8,%9}, {%0,%1,%2,%3};"
        : "+f"(d[0]), "+f"(d[1]), "+f"(d[2]), "+f"(d[3])
        : "r"(a[0]), "r"(a[1]), "r"(a[2]), "r"(a[3]), "r"(b0), "r"(b1));
}
__device__ __forceinline__ float ex2(float x) {
    float y;
    asm("ex2.approx.f32 %0, %1;" : "=f"(y) : "f"(x));
    return y;
}
__device__ __forceinline__ uint32_t pack_hi2(float a, float b, float& ra, float& rb) {
    __nv_bfloat162 h = __floats2bfloat162_rn(a, b);
    ra = a - __bfloat162float(h.x);
    rb = b - __bfloat162float(h.y);
    return *reinterpret_cast<uint32_t*>(&h);
}
__device__ __forceinline__ uint32_t pack_bf2(float a, float b) {
    __nv_bfloat162 h = __floats2bfloat162_rn(a, b);
    return *reinterpret_cast<uint32_t*>(&h);
}
__device__ __forceinline__ uint32_t swz128(int r, int kin) {
    return (uint32_t)(((((kin >> 3) ^ (r & 7)) << 4)) | ((kin & 7) << 1));
}

// ---------------------------------------------------------------------------
// Counter reset (runs first every replay)
// ---------------------------------------------------------------------------
__global__ void reset_ctrs() {
    if (threadIdx.x < 4) g_ctrs[threadIdx.x] = 0;
}

// ---------------------------------------------------------------------------
// Split fp32 -> (hi, lo) bf16, writing PACKED pre-swizzled tiles.
// ---------------------------------------------------------------------------
__global__ void __launch_bounds__(256) split_pack(
    const float* __restrict__ src,
    __nv_bfloat16* __restrict__ hi, __nv_bfloat16* __restrict__ lo,
    int K, int rpb_shift, int n4)
{
    int i = blockIdx.x * blockDim.x + threadIdx.x;
    if (i >= n4) return;
    const int kq = K >> 2;
    int t = i / kq;
    int k = (i - t * kq) * 4;
    float4 v = reinterpret_cast<const float4*>(src)[i];

    __nv_bfloat162 h01 = __floats2bfloat162_rn(v.x, v.y);
    __nv_bfloat162 h23 = __floats2bfloat162_rn(v.z, v.w);
    __nv_bfloat162 l01 = __floats2bfloat162_rn(v.x - __bfloat162float(h01.x),
                                               v.y - __bfloat162float(h01.y));
    __nv_bfloat162 l23 = __floats2bfloat162_rn(v.z - __bfloat162float(h23.x),
                                               v.w - __bfloat162float(h23.y));

    int rb = t >> rpb_shift;
    int r  = t & ((1 << rpb_shift) - 1);
    int ch = k >> 6;
    int kin = k & 63;
    size_t row_byte = ((size_t)((rb * (K >> 6) + ch) << rpb_shift) + r) * 128
                    + swz128(r, kin);
    uint2 hv, lv;
    hv.x = *reinterpret_cast<uint32_t*>(&h01);
    hv.y = *reinterpret_cast<uint32_t*>(&h23);
    lv.x = *reinterpret_cast<uint32_t*>(&l01);
    lv.y = *reinterpret_cast<uint32_t*>(&l23);
    *reinterpret_cast<uint2*>(reinterpret_cast<char*>(hi) + row_byte) = hv;
    *reinterpret_cast<uint2*>(reinterpret_cast<char*>(lo) + row_byte) = lv;
}

// ---------------------------------------------------------------------------
// Mask all-ones check
// ---------------------------------------------------------------------------
__global__ void __launch_bounds__(256) mask_reduce(const int* __restrict__ mask, int n4) {
    int i = blockIdx.x * blockDim.x + threadIdx.x;
    if (i >= n4) return;
    int4 v = reinterpret_cast<const int4*>(mask)[i];
    if (v.x == 0 || v.y == 0 || v.z == 0 || v.w == 0) g_mask_flag = 0;
}

// ---------------------------------------------------------------------------
// PERSISTENT split-bf16 GEMM, bulk loads, 2 CTAs/SM.
// Each CTA steals 64x128 tiles via atomic counter (no wave quantization).
// ---------------------------------------------------------------------------
#define G_AT 8192
#define G_BT 16384
#define G_STG (2*G_AT + 2*G_BT)
#define G_HDR 128
#define GEMM_SMEM (G_HDR + 2*G_STG)

__global__ void __launch_bounds__(128, 2)
gemm_bulk(const __nv_bfloat16* __restrict__ Ahp, const __nv_bfloat16* __restrict__ Alp,
          const __nv_bfloat16* __restrict__ Bhp, const __nv_bfloat16* __restrict__ Blp,
          const float* __restrict__ bias, float* __restrict__ C,
          __nv_bfloat16* __restrict__ Qhi, __nv_bfloat16* __restrict__ Qlo,
          int N, int K, int gx, int total, int* __restrict__ ctr)
{
    extern __shared__ __align__(128) char sm[];
    const uint32_t sm_u = smem_u32(sm);
    const uint32_t stg0 = sm_u + G_HDR;

    const int tid  = threadIdx.x;
    const int lane = tid & 31;
    const int wid  = tid >> 5;
    const int wm   = wid & 1;
    const int wn   = wid >> 1;
    const int nch  = K >> 6;
    const int lr = lane & 15;
    const int lc = lane >> 4;

    if (tid == 0) { mbar_init(sm_u, 1); mbar_init(sm_u + 8, 1); }
    __syncthreads();

    __shared__ int s_tile;
    int phase[2] = {0, 0};

    for (;;) {
        if (tid == 0) s_tile = atomicAdd(ctr, 1);
        __syncthreads();
        const int tt = s_tile;
        if (tt >= total) break;
        const int row0 = (tt / gx) * 64;
        const int col0 = (tt % gx) * 128;

        const int rbA = row0 >> 7;
        const int ra0 = row0 & 127;
        const int nbB = col0 >> 8;
        const int cb0 = col0 & 255;

        auto issue = [&](int ch, int bufi) {
            const uint32_t base = stg0 + bufi * G_STG;
            const uint32_t mb = sm_u + bufi * 8;
            mbar_expect_tx(mb, G_STG);
            size_t ea = ((size_t)(((rbA * nch + ch) << 7) + ra0)) << 6;
            size_t eb = ((size_t)(((nbB * nch + ch) << 8) + cb0)) << 6;
            bulk_g2s(base,               Ahp + ea, G_AT, mb);
            bulk_g2s(base + G_AT,        Alp + ea, G_AT, mb);
            bulk_g2s(base + 2*G_AT,      Bhp + eb, G_BT, mb);
            bulk_g2s(base + 2*G_AT+G_BT, Blp + eb, G_BT, mb);
        };

        float acc[2][8][4];
        #pragma unroll
        for (int i = 0; i < 2; ++i)
            #pragma unroll
            for (int j = 0; j < 8; ++j)
                #pragma unroll
                for (int r = 0; r < 4; ++r) acc[i][j][r] = 0.f;

        if (tid == 0) { issue(0, 0); issue(1, 1); }

        for (int ch = 0; ch < nch; ++ch) {
            const int buf = ch & 1;
            mbar_wait(sm_u + buf * 8, phase[buf]);
            phase[buf] ^= 1;

            const uint32_t base = stg0 + buf * G_STG;
            const uint32_t tAh = base;
            const uint32_t tAl = base + G_AT;
            const uint32_t tBh = base + 2 * G_AT;
            const uint32_t tBl = base + 2 * G_AT + G_BT;

            #pragma unroll
            for (int kk8 = 0; kk8 < 8; kk8 += 2) {
                uint32_t ah[2][4], al[2][4];
                uint32_t bh[8][2], bl[8][2];
                #pragma unroll
                for (int mi = 0; mi < 2; ++mi) {
                    int r = wm * 32 + mi * 16 + lr;
                    uint32_t off = (uint32_t)r * 128 + ((((lc + kk8) ^ (r & 7))) << 4);
                    ldsm_x4(tAh + off, ah[mi]);
                    ldsm_x4(tAl + off, al[mi]);
                }
                #pragma unroll
                for (int n2 = 0; n2 < 4; ++n2) {
                    int r = wn * 64 + n2 * 16 + lr;
                    uint32_t off = (uint32_t)r * 128 + ((((lc + kk8) ^ (r & 7))) << 4);
                    uint32_t th[4], tl[4];
                    ldsm_x4(tBh + off, th);
                    ldsm_x4(tBl + off, tl);
                    bh[n2*2+0][0] = th[0]; bh[n2*2+0][1] = th[2];
                    bh[n2*2+1][0] = th[1]; bh[n2*2+1][1] = th[3];
                    bl[n2*2+0][0] = tl[0]; bl[n2*2+0][1] = tl[2];
                    bl[n2*2+1][0] = tl[1]; bl[n2*2+1][1] = tl[3];
                }
                #pragma unroll
                for (int mi = 0; mi < 2; ++mi)
                    #pragma unroll
                    for (int nj = 0; nj < 8; ++nj)
                        mma_bf16(acc[mi][nj], ah[mi], bh[nj][0], bh[nj][1]);
                #pragma unroll
                for (int mi = 0; mi < 2; ++mi)
                    #pragma unroll
                    for (int nj = 0; nj < 8; ++nj)
                        mma_bf16(acc[mi][nj], ah[mi], bl[nj][0], bl[nj][1]);
                #pragma unroll
                for (int mi = 0; mi < 2; ++mi)
                    #pragma unroll
                    for (int nj = 0; nj < 8; ++nj)
                        mma_bf16(acc[mi][nj], al[mi], bh[nj][0], bh[nj][1]);
            }
            __syncthreads();
            if (tid == 0 && ch + 2 < nch) issue(ch + 2, buf);
        }

        // ---- epilogue ----
        #pragma unroll
        for (int mi = 0; mi < 2; ++mi) {
            #pragma unroll
            for (int nj = 0; nj < 8; ++nj) {
                int col = col0 + wn * 64 + nj * 8 + (lane & 3) * 2;
                float b0 = bias[col], b1 = bias[col + 1];
                #pragma unroll
                for (int hh2 = 0; hh2 < 2; ++hh2) {
                    int row = row0 + wm * 32 + mi * 16 + (lane >> 2) + hh2 * 8;
                    float o0 = acc[mi][nj][hh2 * 2 + 0] + b0;
                    float o1 = acc[mi][nj][hh2 * 2 + 1] + b1;
                    if (Qhi) {
                        int comp = col >> 10;
                        float sc = (comp == 0) ? 0.18033688011112042f : 1.0f;
                        o0 *= sc; o1 *= sc;
                        int hd = (col >> 6) & 15;
                        int d  = col & 63;
                        int bg = row >> 11;
                        int t2 = row & 2047;
                        size_t row_byte =
                            ((size_t)(((comp * 2 + bg) * 16 + hd) * 2048 + t2)) * 128
                            + swz128(t2, d);
                        float r0, r1;
                        uint32_t hi2 = pack_hi2(o0, o1, r0, r1);
                        uint32_t lo2 = pack_bf2(r0, r1);
                        *reinterpret_cast<uint32_t*>(reinterpret_cast<char*>(Qhi) + row_byte) = hi2;
                        *reinterpret_cast<uint32_t*>(reinterpret_cast<char*>(Qlo) + row_byte) = lo2;
                    } else {
                        float2 o; o.x = o0; o.y = o1;
                        *reinterpret_cast<float2*>(C + (size_t)row * N + col) = o;
                    }
                }
            }
        }
    }
}

// ---------------------------------------------------------------------------
// PERSISTENT flash attention: 128 threads, q-tile 64, 3 CTAs/SM.
// Tiles stolen via atomic counter; Q staged in kv buf0 per tile.
// ---------------------------------------------------------------------------
#define A_KT 8192
#define A_STG (4 * A_KT)
#define A_HDR 128
#define ATTN_SMEM (A_HDR + 2 * A_STG)

__global__ void __launch_bounds__(128, 3)
attn_bulk(const __nv_bfloat16* __restrict__ qph, const __nv_bfloat16* __restrict__ qpl,
          const int* __restrict__ mask,
          __nv_bfloat16* __restrict__ yh, __nv_bfloat16* __restrict__ yl,
          int total, int* __restrict__ ctr)
{
    extern __shared__ __align__(128) char sm[];
    const uint32_t sm_u = smem_u32(sm);
    const uint32_t kv0s = sm_u + A_HDR;

    const int tid  = threadIdx.x;
    const int lane = tid & 31;
    const int wid  = tid >> 5;
    const int lr = lane & 15;
    const int lc = lane >> 4;
    const int r0 = lane >> 2;

    const size_t CS = (size_t)2 * 16 * 2048 * 64;
    const int allones = g_mask_flag;

    if (tid == 0) {
        mbar_init(sm_u, 1);
        mbar_init(sm_u + 8, 1);
        mbar_init(sm_u + 16, 1);
    }
    __syncthreads();

    __shared__ int s_tile;
    int qphase = 0;
    int phase[2] = {0, 0};
    const int NKV = TT / 64;

    for (;;) {
        if (tid == 0) s_tile = atomicAdd(ctr, 1);
        __syncthreads();
        const int tt = s_tile;
        if (tt >= total) break;
        const int q0 = (tt & 31) * 64;
        const int bh = tt >> 5;
        const int b  = bh >> 4;
        const int h  = bh & 15;
        const size_t bh_base = ((size_t)(b * 16 + h) * 2048) * 64;

        auto issue_kv = [&](int kt, int bufi) {
            const uint32_t mb = sm_u + 8 + bufi * 8;
            const uint32_t base = kv0s + bufi * A_STG;
            const size_t koff = bh_base + (size_t)(kt * 64) * 64;
            mbar_expect_tx(mb, A_STG);
            bulk_g2s(base,            qph + CS + koff,     A_KT, mb);
            bulk_g2s(base + A_KT,     qpl + CS + koff,     A_KT, mb);
            bulk_g2s(base + 2*A_KT,   qph + 2*CS + koff,   A_KT, mb);
            bulk_g2s(base + 3*A_KT,   qpl + 2*CS + koff,   A_KT, mb);
        };

        // ---- stage Q inside kv buffer 0, read fragments, free it ----
        if (tid == 0) {
            mbar_expect_tx(sm_u, 16384);
            bulk_g2s(kv0s,        qph + bh_base + (size_t)q0 * 64, 8192, sm_u);
            bulk_g2s(kv0s + 8192, qpl + bh_base + (size_t)q0 * 64, 8192, sm_u);
        }
        mbar_wait(sm_u, qphase);
        qphase ^= 1;
        uint32_t qfh[4][4], qfl[4][4];
        #pragma unroll
        for (int ks = 0; ks < 4; ++ks) {
            int r = wid * 16 + lr;
            uint32_t off = (uint32_t)r * 128 + (((lc + 2 * ks) ^ (r & 7)) << 4);
            ldsm_x4(kv0s + off, qfh[ks]);
            ldsm_x4(kv0s + 8192 + off, qfl[ks]);
        }
        __syncthreads();
        if (tid == 0) { issue_kv(0, 0); issue_kv(1, 1); }

        float accO[8][4];
        #pragma unroll
        for (int n = 0; n < 8; ++n)
            #pragma unroll
            for (int r = 0; r < 4; ++r) accO[n][r] = 0.f;
        float mrow[2] = {-1e30f, -1e30f};
        float lrow[2] = {0.f, 0.f};

        for (int kt = 0; kt < NKV; ++kt) {
            const int buf = kt & 1;
            mbar_wait(sm_u + 8 + buf * 8, phase[buf]);
            phase[buf] ^= 1;

            const uint32_t base = kv0s + buf * A_STG;
            const uint32_t tKh = base;
            const uint32_t tKl = base + A_KT;
            const uint32_t tVh = base + 2 * A_KT;
            const uint32_t tVl = base + 3 * A_KT;

            float s[8][4];
            #pragma unroll
            for (int n = 0; n < 8; ++n)
                #pragma unroll
                for (int r = 0; r < 4; ++r) s[n][r] = 0.f;

            #pragma unroll
            for (int ks = 0; ks < 4; ++ks) {
                uint32_t kh[8][2], kl[8][2];
                #pragma unroll
                for (int n2 = 0; n2 < 4; ++n2) {
                    int r = n2 * 16 + lr;
                    uint32_t off = (uint32_t)r * 128 + (((lc + 2 * ks) ^ (r & 7)) << 4);
                    uint32_t th[4], tl[4];
                    ldsm_x4(tKh + off, th);
                    ldsm_x4(tKl + off, tl);
                    kh[n2*2+0][0] = th[0]; kh[n2*2+0][1] = th[2];
                    kh[n2*2+1][0] = th[1]; kh[n2*2+1][1] = th[3];
                    kl[n2*2+0][0] = tl[0]; kl[n2*2+0][1] = tl[2];
                    kl[n2*2+1][0] = tl[1]; kl[n2*2+1][1] = tl[3];
                }
                #pragma unroll
                for (int nj = 0; nj < 8; ++nj)
                    mma_bf16(s[nj], qfh[ks], kh[nj][0], kh[nj][1]);
                #pragma unroll
                for (int nj = 0; nj < 8; ++nj)
                    mma_bf16(s[nj], qfh[ks], kl[nj][0], kl[nj][1]);
                #pragma unroll
                for (int nj = 0; nj < 8; ++nj)
                    mma_bf16(s[nj], qfl[ks], kh[nj][0], kh[nj][1]);
            }

            if (!allones) {
                const int kvb = kt * 64;
                int qrow = b * TT + 0;  // mask is [1,1,T,T]: row index is q position
                qrow = q0 + wid * 16 + r0;
                #pragma unroll
                for (int nj = 0; nj < 8; ++nj) {
                    int c = kvb + nj * 8 + (lane & 3) * 2;
                    const int* m0 = mask + (size_t)qrow * TT + c;
                    const int* m1 = mask + (size_t)(qrow + 8) * TT + c;
                    if (m0[0] == 0) s[nj][0] = -1e30f;
                    if (m0[1] == 0) s[nj][1] = -1e30f;
                    if (m1[0] == 0) s[nj][2] = -1e30f;
                    if (m1[1] == 0) s[nj][3] = -1e30f;
                }
            }

            float rm0 = -1e30f, rm1 = -1e30f;
            #pragma unroll
            for (int nj = 0; nj < 8; ++nj) {
                rm0 = fmaxf(rm0, fmaxf(s[nj][0], s[nj][1]));
                rm1 = fmaxf(rm1, fmaxf(s[nj][2], s[nj][3]));
            }
            rm0 = fmaxf(rm0, __shfl_xor_sync(0xffffffffu, rm0, 1));
            rm0 = fmaxf(rm0, __shfl_xor_sync(0xffffffffu, rm0, 2));
            rm1 = fmaxf(rm1, __shfl_xor_sync(0xffffffffu, rm1, 1));
            rm1 = fmaxf(rm1, __shfl_xor_sync(0xffffffffu, rm1, 2));

            float mn0 = fmaxf(mrow[0], rm0);
            float mn1 = fmaxf(mrow[1], rm1);
            float c0 = ex2(mrow[0] - mn0);
            float c1 = ex2(mrow[1] - mn1);
            float ps0 = 0.f, ps1 = 0.f;
            #pragma unroll
            for (int nj = 0; nj < 8; ++nj) {
                s[nj][0] = ex2(s[nj][0] - mn0);
                s[nj][1] = ex2(s[nj][1] - mn0);
                s[nj][2] = ex2(s[nj][2] - mn1);
                s[nj][3] = ex2(s[nj][3] - mn1);
                ps0 += s[nj][0] + s[nj][1];
                ps1 += s[nj][2] + s[nj][3];
            }
            ps0 += __shfl_xor_sync(0xffffffffu, ps0, 1);
            ps0 += __shfl_xor_sync(0xffffffffu, ps0, 2);
            ps1 += __shfl_xor_sync(0xffffffffu, ps1, 1);
            ps1 += __shfl_xor_sync(0xffffffffu, ps1, 2);
            lrow[0] = lrow[0] * c0 + ps0;
            lrow[1] = lrow[1] * c1 + ps1;
            mrow[0] = mn0; mrow[1] = mn1;
            #pragma unroll
            for (int nj = 0; nj < 8; ++nj) {
                accO[nj][0] *= c0; accO[nj][1] *= c0;
                accO[nj][2] *= c1; accO[nj][3] *= c1;
            }

            #pragma unroll
            for (int ks = 0; ks < 4; ++ks) {
                uint32_t pfh[4], pfl[4];
                {
                    float ra, rb2;
                    pfh[0] = pack_hi2(s[2*ks][0],   s[2*ks][1],   ra, rb2);
                    pfl[0] = pack_bf2(ra, rb2);
                    pfh[1] = pack_hi2(s[2*ks][2],   s[2*ks][3],   ra, rb2);
                    pfl[1] = pack_bf2(ra, rb2);
                    pfh[2] = pack_hi2(s[2*ks+1][0], s[2*ks+1][1], ra, rb2);
                    pfl[2] = pack_bf2(ra, rb2);
                    pfh[3] = pack_hi2(s[2*ks+1][2], s[2*ks+1][3], ra, rb2);
                    pfl[3] = pack_bf2(ra, rb2);
                }
                uint32_t vh[4][4], vl[4][4];
                #pragma unroll
                for (int g = 0; g < 4; ++g) {
                    int r = ks * 16 + lr;
                    uint32_t off = (uint32_t)r * 128 + (((lc + 2 * g) ^ (r & 7)) << 4);
                    ldsm_x4_t(tVh + off, vh[g]);
                    ldsm_x4_t(tVl + off, vl[g]);
                }
                #pragma unroll
                for (int g = 0; g < 4; ++g) {
                    mma_bf16(accO[2*g],   pfh, vh[g][0], vh[g][1]);
                    mma_bf16(accO[2*g+1], pfh, vh[g][2], vh[g][3]);
                }
                #pragma unroll
                for (int g = 0; g < 4; ++g) {
                    mma_bf16(accO[2*g],   pfh, vl[g][0], vl[g][1]);
                    mma_bf16(accO[2*g+1], pfh, vl[g][2], vl[g][3]);
                }
                #pragma unroll
                for (int g = 0; g < 4; ++g) {
                    mma_bf16(accO[2*g],   pfl, vh[g][0], vh[g][1]);
                    mma_bf16(accO[2*g+1], pfl, vh[g][2], vh[g][3]);
                }
            }
            __syncthreads();
            if (tid == 0 && kt + 2 < NKV) issue_kv(kt + 2, buf);
        }

        // ---- epilogue: y packed [rb][ch=h][r][64] SW128 ----
        float inv0 = 1.f / lrow[0];
        float inv1 = 1.f / lrow[1];
        int gr_a = b * TT + q0 + wid * 16 + r0;
        int gr_b = gr_a + 8;
        #pragma unroll
        for (int nj = 0; nj < 8; ++nj) {
            int kin = nj * 8 + (lane & 3) * 2;
            float ra, rb2;
            uint32_t hi2, lo2;
            {
                int rb = gr_a >> 7, r = gr_a & 127;
                size_t row_byte = ((size_t)((rb * 16 + h) * 128 + r)) * 128 + swz128(r, kin);
                hi2 = pack_hi2(accO[nj][0] * inv0, accO[nj][1] * inv0, ra, rb2);
                lo2 = pack_bf2(ra, rb2);
                *reinterpret_cast<uint32_t*>(reinterpret_cast<char*>(yh) + row_byte) = hi2;
                *reinterpret_cast<uint32_t*>(reinterpret_cast<char*>(yl) + row_byte) = lo2;
            }
            {
                int rb = gr_b >> 7, r = gr_b & 127;
                size_t row_byte = ((size_t)((rb * 16 + h) * 128 + r)) * 128 + swz128(r, kin);
                hi2 = pack_hi2(accO[nj][2] * inv1, accO[nj][3] * inv1, ra, rb2);
                lo2 = pack_bf2(ra, rb2);
                *reinterpret_cast<uint32_t*>(reinterpret_cast<char*>(yh) + row_byte) = hi2;
                *reinterpret_cast<uint32_t*>(reinterpret_cast<char*>(yl) + row_byte) = lo2;
            }
        }
        __syncthreads();   // epilogue done before next tile's Q overwrites buf0
    }
}

// ---------------------------------------------------------------------------
extern "C" void kernel_launch(void* const* d_in, const int* in_sizes, int n_in,
                              void* d_out, int out_size)
{
    const float* x     = (const float*)d_in[0];
    const int*   mask  = (const int*)d_in[1];
    const float* w_qkv = (const float*)d_in[2];
    const float* b_qkv = (const float*)d_in[3];
    const float* w_out = (const float*)d_in[4];
    const float* b_out = (const float*)d_in[5];
    float* out = (float*)d_out;

    __nv_bfloat16 *xh, *xl, *wqh, *wql, *woh, *wol, *qph, *qpl, *yh, *yl;
    int* ctrs;
    cudaGetSymbolAddress((void**)&xh, g_xp_hi);
    cudaGetSymbolAddress((void**)&xl, g_xp_lo);
    cudaGetSymbolAddress((void**)&wqh, g_wqkvp_hi);
    cudaGetSymbolAddress((void**)&wql, g_wqkvp_lo);
    cudaGetSymbolAddress((void**)&woh, g_woutp_hi);
    cudaGetSymbolAddress((void**)&wol, g_woutp_lo);
    cudaGetSymbolAddress((void**)&qph, g_qkvp_hi);
    cudaGetSymbolAddress((void**)&qpl, g_qkvp_lo);
    cudaGetSymbolAddress((void**)&yh, g_yp_hi);
    cudaGetSymbolAddress((void**)&yl, g_yp_lo);
    cudaGetSymbolAddress((void**)&ctrs, g_ctrs);

    cudaFuncSetAttribute(gemm_bulk,
                         cudaFuncAttributeMaxDynamicSharedMemorySize, GEMM_SMEM);
    cudaFuncSetAttribute(attn_bulk,
                         cudaFuncAttributeMaxDynamicSharedMemorySize, ATTN_SMEM);

    reset_ctrs<<<1, 32>>>();
    {
        int n4 = MM * DD / 4;
        split_pack<<<(n4 + 255) / 256, 256>>>(x, xh, xl, DD, 7, n4);
        n4 = 3 * DD * DD / 4;
        split_pack<<<(n4 + 255) / 256, 256>>>(w_qkv, wqh, wql, DD, 8, n4);
        n4 = DD * DD / 4;
        split_pack<<<(n4 + 255) / 256, 256>>>(w_out, woh, wol, DD, 8, n4);
        int m4 = TT * TT / 4;
        mask_reduce<<<(m4 + 255) / 256, 256>>>(mask, m4);
    }

    // 1) QKV projection (persistent): tiles = 24 x 64 = 1536
    gemm_bulk<<<2 * NSM, 128, GEMM_SMEM>>>(
        xh, xl, wqh, wql, b_qkv, nullptr, qph, qpl,
        3 * DD, DD, 3 * DD / 128, (3 * DD / 128) * (MM / 64), ctrs + 0);

    // 2) attention (persistent): tiles = 32 q-tiles x 32 bh = 1024
    attn_bulk<<<3 * NSM, 128, ATTN_SMEM>>>(
        qph, qpl, mask, yh, yl, (TT / 64) * BB * HH, ctrs + 1);

    // 3) output projection (persistent): tiles = 8 x 64 = 512
    gemm_bulk<<<2 * NSM, 128, GEMM_SMEM>>>(
        yh, yl, woh, wol, b_out, out, nullptr, nullptr,
        DD, DD, DD / 128, (DD / 128) * (MM / 64), ctrs + 2);
}

// round 13
// speedup vs baseline: 1.0355x; 1.0355x over previous
#include <cuda_runtime.h>
#include <cuda_bf16.h>
#include <cstdint>
#include <cstddef>

#define BB 2
#define TT 2048
#define DD 1024
#define HH 16
#define HD 64
#define MM (BB*TT)
#define NSM 148

// ---------------- packed, pre-swizzled scratch (allocation-free) ----------------
__device__ __nv_bfloat16 g_xp_hi[(size_t)MM * DD];
__device__ __nv_bfloat16 g_xp_lo[(size_t)MM * DD];
__device__ __nv_bfloat16 g_wqkvp_hi[(size_t)3 * DD * DD];
__device__ __nv_bfloat16 g_wqkvp_lo[(size_t)3 * DD * DD];
__device__ __nv_bfloat16 g_woutp_hi[(size_t)DD * DD];
__device__ __nv_bfloat16 g_woutp_lo[(size_t)DD * DD];
__device__ __nv_bfloat16 g_qkvp_hi[(size_t)3 * MM * DD];
__device__ __nv_bfloat16 g_qkvp_lo[(size_t)3 * MM * DD];
__device__ __nv_bfloat16 g_yp_hi[(size_t)MM * DD];
__device__ __nv_bfloat16 g_yp_lo[(size_t)MM * DD];
__device__ int g_mask_flag = 1;
__device__ int g_ctrs[4];

// ---------------- base-target PTX helpers ----------------
__device__ __forceinline__ uint32_t smem_u32(const void* p) {
    uint32_t a;
    asm("{ .reg .u64 t; cvta.to.shared.u64 t, %1; cvt.u32.u64 %0, t; }"
        : "=r"(a) : "l"(p));
    return a;
}
__device__ __forceinline__ void mbar_init(uint32_t mbar, uint32_t cnt) {
    asm volatile("mbarrier.init.shared.b64 [%0], %1;" :: "r"(mbar), "r"(cnt) : "memory");
}
__device__ __forceinline__ void mbar_expect_tx(uint32_t mbar, uint32_t bytes) {
    asm volatile("mbarrier.arrive.expect_tx.shared.b64 _, [%0], %1;"
                 :: "r"(mbar), "r"(bytes) : "memory");
}
__device__ __forceinline__ void mbar_wait(uint32_t mbar, uint32_t parity) {
    asm volatile(
        "{\n\t.reg .pred P;\n\t"
        "WL_%=:\n\t"
        "mbarrier.try_wait.parity.acquire.cta.shared::cta.b64 P, [%0], %1, 0x989680;\n\t"
        "@P bra WD_%=;\n\t"
        "bra WL_%=;\n\t"
        "WD_%=:\n\t}"
        :: "r"(mbar), "r"(parity) : "memory");
}
__device__ __forceinline__ void bulk_g2s(uint32_t dst, const void* src,
                                         uint32_t bytes, uint32_t mbar) {
    asm volatile(
        "cp.async.bulk.shared::cluster.global.mbarrier::complete_tx::bytes "
        "[%0], [%1], %2, [%3];"
        :: "r"(dst), "l"(src), "r"(bytes), "r"(mbar) : "memory");
}
__device__ __forceinline__ void ldsm_x4(uint32_t addr, uint32_t r[4]) {
    asm volatile("ldmatrix.sync.aligned.m8n8.x4.shared.b16 {%0,%1,%2,%3}, [%4];"
                 : "=r"(r[0]), "=r"(r[1]), "=r"(r[2]), "=r"(r[3]) : "r"(addr));
}
__device__ __forceinline__ void ldsm_x4_t(uint32_t addr, uint32_t r[4]) {
    asm volatile("ldmatrix.sync.aligned.m8n8.x4.trans.shared.b16 {%0,%1,%2,%3}, [%4];"
                 : "=r"(r[0]), "=r"(r[1]), "=r"(r[2]), "=r"(r[3]) : "r"(addr));
}
__device__ __forceinline__ void mma_bf16(float d[4], const uint32_t a[4],
                                         uint32_t b0, uint32_t b1) {
    asm volatile(
        "mma.sync.aligned.m16n8k16.row.col.f32.bf16.bf16.f32 "
        "{%0,%1,%2,%3}, {%4,%5,%6,%7}, {%8,%9}, {%0,%1,%2,%3};"
        : "+f"(d[0]), "+f"(d[1]), "+f"(d[2]), "+f"(d[3])
        : "r"(a[0]), "r"(a[1]), "r"(a[2]), "r"(a[3]), "r"(b0), "r"(b1));
}
__device__ __forceinline__ float ex2(float x) {
    float y;
    asm("ex2.approx.f32 %0, %1;" : "=f"(y) : "f"(x));
    return y;
}
__device__ __forceinline__ uint32_t pack_hi2(float a, float b, float& ra, float& rb) {
    __nv_bfloat162 h = __floats2bfloat162_rn(a, b);
    ra = a - __bfloat162float(h.x);
    rb = b - __bfloat162float(h.y);
    return *reinterpret_cast<uint32_t*>(&h);
}
__device__ __forceinline__ uint32_t pack_bf2(float a, float b) {
    __nv_bfloat162 h = __floats2bfloat162_rn(a, b);
    return *reinterpret_cast<uint32_t*>(&h);
}
__device__ __forceinline__ uint32_t swz128(int r, int kin) {
    return (uint32_t)(((((kin >> 3) ^ (r & 7)) << 4)) | ((kin & 7) << 1));
}

// ---------------------------------------------------------------------------
// FUSED prep: splits (x, w_qkv, w_out), mask all-ones check, counter reset.
// All split tensors have K=1024 (kq=256 float4 groups per row).
// ---------------------------------------------------------------------------
#define N4X  (MM * DD / 4)            // 1048576
#define N4WQ (3 * DD * DD / 4)        // 786432
#define N4WO (DD * DD / 4)            // 262144
#define N4M  (TT * TT / 4)            // 1048576
#define PREP_TOT (N4X + N4WQ + N4WO + N4M)

__device__ __forceinline__ void do_split(
    const float* __restrict__ src, __nv_bfloat16* __restrict__ hi,
    __nv_bfloat16* __restrict__ lo, int j, int rpb_shift)
{
    int t = j >> 8;                  // row (kq = 256)
    int k = (j & 255) << 2;
    float4 v = reinterpret_cast<const float4*>(src)[j];

    __nv_bfloat162 h01 = __floats2bfloat162_rn(v.x, v.y);
    __nv_bfloat162 h23 = __floats2bfloat162_rn(v.z, v.w);
    __nv_bfloat162 l01 = __floats2bfloat162_rn(v.x - __bfloat162float(h01.x),
                                               v.y - __bfloat162float(h01.y));
    __nv_bfloat162 l23 = __floats2bfloat162_rn(v.z - __bfloat162float(h23.x),
                                               v.w - __bfloat162float(h23.y));
    int rb = t >> rpb_shift;
    int r  = t & ((1 << rpb_shift) - 1);
    int ch = k >> 6;
    int kin = k & 63;
    size_t row_byte = ((size_t)((rb * 16 + ch) << rpb_shift) + r) * 128
                    + swz128(r, kin);
    uint2 hv, lv;
    hv.x = *reinterpret_cast<uint32_t*>(&h01);
    hv.y = *reinterpret_cast<uint32_t*>(&h23);
    lv.x = *reinterpret_cast<uint32_t*>(&l01);
    lv.y = *reinterpret_cast<uint32_t*>(&l23);
    *reinterpret_cast<uint2*>(reinterpret_cast<char*>(hi) + row_byte) = hv;
    *reinterpret_cast<uint2*>(reinterpret_cast<char*>(lo) + row_byte) = lv;
}

__global__ void __launch_bounds__(256) prep_all(
    const float* __restrict__ x, const float* __restrict__ wqkv,
    const float* __restrict__ wout, const int* __restrict__ mask,
    __nv_bfloat16* __restrict__ xh, __nv_bfloat16* __restrict__ xl,
    __nv_bfloat16* __restrict__ wqh, __nv_bfloat16* __restrict__ wql,
    __nv_bfloat16* __restrict__ woh, __nv_bfloat16* __restrict__ wol)
{
    int i = blockIdx.x * 256 + threadIdx.x;
    if (blockIdx.x == 0 && threadIdx.x < 4) g_ctrs[threadIdx.x] = 0;
    if (i < N4X) {
        do_split(x, xh, xl, i, 7);
    } else if (i < N4X + N4WQ) {
        do_split(wqkv, wqh, wql, i - N4X, 8);
    } else if (i < N4X + N4WQ + N4WO) {
        do_split(wout, woh, wol, i - N4X - N4WQ, 8);
    } else if (i < PREP_TOT) {
        int4 v = reinterpret_cast<const int4*>(mask)[i - N4X - N4WQ - N4WO];
        if (v.x == 0 || v.y == 0 || v.z == 0 || v.w == 0) g_mask_flag = 0;
    }
}

// ---------------------------------------------------------------------------
// PERSISTENT split-bf16 GEMM, bulk loads, 2 CTAs/SM (R12-verified).
// ---------------------------------------------------------------------------
#define G_AT 8192
#define G_BT 16384
#define G_STG (2*G_AT + 2*G_BT)
#define G_HDR 128
#define GEMM_SMEM (G_HDR + 2*G_STG)

__global__ void __launch_bounds__(128, 2)
gemm_bulk(const __nv_bfloat16* __restrict__ Ahp, const __nv_bfloat16* __restrict__ Alp,
          const __nv_bfloat16* __restrict__ Bhp, const __nv_bfloat16* __restrict__ Blp,
          const float* __restrict__ bias, float* __restrict__ C,
          __nv_bfloat16* __restrict__ Qhi, __nv_bfloat16* __restrict__ Qlo,
          int N, int K, int gx, int total, int* __restrict__ ctr)
{
    extern __shared__ __align__(128) char sm[];
    const uint32_t sm_u = smem_u32(sm);
    const uint32_t stg0 = sm_u + G_HDR;

    const int tid  = threadIdx.x;
    const int lane = tid & 31;
    const int wid  = tid >> 5;
    const int wm   = wid & 1;
    const int wn   = wid >> 1;
    const int nch  = K >> 6;
    const int lr = lane & 15;
    const int lc = lane >> 4;

    if (tid == 0) { mbar_init(sm_u, 1); mbar_init(sm_u + 8, 1); }
    __syncthreads();

    __shared__ int s_tile;
    int phase[2] = {0, 0};

    for (;;) {
        if (tid == 0) s_tile = atomicAdd(ctr, 1);
        __syncthreads();
        const int tt = s_tile;
        if (tt >= total) break;
        const int row0 = (tt / gx) * 64;
        const int col0 = (tt % gx) * 128;

        const int rbA = row0 >> 7;
        const int ra0 = row0 & 127;
        const int nbB = col0 >> 8;
        const int cb0 = col0 & 255;

        auto issue = [&](int ch, int bufi) {
            const uint32_t base = stg0 + bufi * G_STG;
            const uint32_t mb = sm_u + bufi * 8;
            mbar_expect_tx(mb, G_STG);
            size_t ea = ((size_t)(((rbA * nch + ch) << 7) + ra0)) << 6;
            size_t eb = ((size_t)(((nbB * nch + ch) << 8) + cb0)) << 6;
            bulk_g2s(base,               Ahp + ea, G_AT, mb);
            bulk_g2s(base + G_AT,        Alp + ea, G_AT, mb);
            bulk_g2s(base + 2*G_AT,      Bhp + eb, G_BT, mb);
            bulk_g2s(base + 2*G_AT+G_BT, Blp + eb, G_BT, mb);
        };

        float acc[2][8][4];
        #pragma unroll
        for (int i = 0; i < 2; ++i)
            #pragma unroll
            for (int j = 0; j < 8; ++j)
                #pragma unroll
                for (int r = 0; r < 4; ++r) acc[i][j][r] = 0.f;

        if (tid == 0) { issue(0, 0); issue(1, 1); }

        for (int ch = 0; ch < nch; ++ch) {
            const int buf = ch & 1;
            mbar_wait(sm_u + buf * 8, phase[buf]);
            phase[buf] ^= 1;

            const uint32_t base = stg0 + buf * G_STG;
            const uint32_t tAh = base;
            const uint32_t tAl = base + G_AT;
            const uint32_t tBh = base + 2 * G_AT;
            const uint32_t tBl = base + 2 * G_AT + G_BT;

            #pragma unroll
            for (int kk8 = 0; kk8 < 8; kk8 += 2) {
                uint32_t ah[2][4], al[2][4];
                uint32_t bh[8][2], bl[8][2];
                #pragma unroll
                for (int mi = 0; mi < 2; ++mi) {
                    int r = wm * 32 + mi * 16 + lr;
                    uint32_t off = (uint32_t)r * 128 + ((((lc + kk8) ^ (r & 7))) << 4);
                    ldsm_x4(tAh + off, ah[mi]);
                    ldsm_x4(tAl + off, al[mi]);
                }
                #pragma unroll
                for (int n2 = 0; n2 < 4; ++n2) {
                    int r = wn * 64 + n2 * 16 + lr;
                    uint32_t off = (uint32_t)r * 128 + ((((lc + kk8) ^ (r & 7))) << 4);
                    uint32_t th[4], tl[4];
                    ldsm_x4(tBh + off, th);
                    ldsm_x4(tBl + off, tl);
                    bh[n2*2+0][0] = th[0]; bh[n2*2+0][1] = th[2];
                    bh[n2*2+1][0] = th[1]; bh[n2*2+1][1] = th[3];
                    bl[n2*2+0][0] = tl[0]; bl[n2*2+0][1] = tl[2];
                    bl[n2*2+1][0] = tl[1]; bl[n2*2+1][1] = tl[3];
                }
                #pragma unroll
                for (int mi = 0; mi < 2; ++mi)
                    #pragma unroll
                    for (int nj = 0; nj < 8; ++nj)
                        mma_bf16(acc[mi][nj], ah[mi], bh[nj][0], bh[nj][1]);
                #pragma unroll
                for (int mi = 0; mi < 2; ++mi)
                    #pragma unroll
                    for (int nj = 0; nj < 8; ++nj)
                        mma_bf16(acc[mi][nj], ah[mi], bl[nj][0], bl[nj][1]);
                #pragma unroll
                for (int mi = 0; mi < 2; ++mi)
                    #pragma unroll
                    for (int nj = 0; nj < 8; ++nj)
                        mma_bf16(acc[mi][nj], al[mi], bh[nj][0], bh[nj][1]);
            }
            __syncthreads();
            if (tid == 0 && ch + 2 < nch) issue(ch + 2, buf);
        }

        // ---- epilogue ----
        #pragma unroll
        for (int mi = 0; mi < 2; ++mi) {
            #pragma unroll
            for (int nj = 0; nj < 8; ++nj) {
                int col = col0 + wn * 64 + nj * 8 + (lane & 3) * 2;
                float b0 = bias[col], b1 = bias[col + 1];
                #pragma unroll
                for (int hh2 = 0; hh2 < 2; ++hh2) {
                    int row = row0 + wm * 32 + mi * 16 + (lane >> 2) + hh2 * 8;
                    float o0 = acc[mi][nj][hh2 * 2 + 0] + b0;
                    float o1 = acc[mi][nj][hh2 * 2 + 1] + b1;
                    if (Qhi) {
                        int comp = col >> 10;
                        float sc = (comp == 0) ? 0.18033688011112042f : 1.0f;
                        o0 *= sc; o1 *= sc;
                        int hd = (col >> 6) & 15;
                        int d  = col & 63;
                        int bg = row >> 11;
                        int t2 = row & 2047;
                        size_t row_byte =
                            ((size_t)(((comp * 2 + bg) * 16 + hd) * 2048 + t2)) * 128
                            + swz128(t2, d);
                        float r0, r1;
                        uint32_t hi2 = pack_hi2(o0, o1, r0, r1);
                        uint32_t lo2 = pack_bf2(r0, r1);
                        *reinterpret_cast<uint32_t*>(reinterpret_cast<char*>(Qhi) + row_byte) = hi2;
                        *reinterpret_cast<uint32_t*>(reinterpret_cast<char*>(Qlo) + row_byte) = lo2;
                    } else {
                        float2 o; o.x = o0; o.y = o1;
                        *reinterpret_cast<float2*>(C + (size_t)row * N + col) = o;
                    }
                }
            }
        }
    }
}

// ---------------------------------------------------------------------------
// Flash attention (R11-verified): grid-launched, 128 threads, q-tile 64,
// 3 CTAs/SM, Q staged in kv buf0, 2-stage bulk KV, log2 softmax.
// ---------------------------------------------------------------------------
#define A_KT 8192
#define A_STG (4 * A_KT)
#define A_HDR 128
#define ATTN_SMEM (A_HDR + 2 * A_STG)

__global__ void __launch_bounds__(128, 3)
attn_bulk(const __nv_bfloat16* __restrict__ qph, const __nv_bfloat16* __restrict__ qpl,
          const int* __restrict__ mask,
          __nv_bfloat16* __restrict__ yh, __nv_bfloat16* __restrict__ yl)
{
    extern __shared__ __align__(128) char sm[];
    const uint32_t sm_u = smem_u32(sm);
    const uint32_t kv0s = sm_u + A_HDR;

    const int tid  = threadIdx.x;
    const int lane = tid & 31;
    const int wid  = tid >> 5;
    const int q0   = blockIdx.x * 64;
    const int b    = blockIdx.y >> 4;
    const int h    = blockIdx.y & 15;
    const int lr = lane & 15;
    const int lc = lane >> 4;
    const int r0 = lane >> 2;

    const size_t CS = (size_t)2 * 16 * 2048 * 64;
    const size_t bh_base = ((size_t)(b * 16 + h) * 2048) * 64;

    if (tid == 0) {
        mbar_init(sm_u, 1);
        mbar_init(sm_u + 8, 1);
        mbar_init(sm_u + 16, 1);
    }
    __syncthreads();

    auto issue_kv = [&](int kt, int bufi) {
        const uint32_t mb = sm_u + 8 + bufi * 8;
        const uint32_t base = kv0s + bufi * A_STG;
        const size_t koff = bh_base + (size_t)(kt * 64) * 64;
        mbar_expect_tx(mb, A_STG);
        bulk_g2s(base,            qph + CS + koff,     A_KT, mb);
        bulk_g2s(base + A_KT,     qpl + CS + koff,     A_KT, mb);
        bulk_g2s(base + 2*A_KT,   qph + 2*CS + koff,   A_KT, mb);
        bulk_g2s(base + 3*A_KT,   qpl + 2*CS + koff,   A_KT, mb);
    };

    if (tid == 0) {
        mbar_expect_tx(sm_u, 16384);
        bulk_g2s(kv0s,        qph + bh_base + (size_t)q0 * 64, 8192, sm_u);
        bulk_g2s(kv0s + 8192, qpl + bh_base + (size_t)q0 * 64, 8192, sm_u);
    }
    mbar_wait(sm_u, 0);
    uint32_t qfh[4][4], qfl[4][4];
    #pragma unroll
    for (int ks = 0; ks < 4; ++ks) {
        int r = wid * 16 + lr;
        uint32_t off = (uint32_t)r * 128 + (((lc + 2 * ks) ^ (r & 7)) << 4);
        ldsm_x4(kv0s + off, qfh[ks]);
        ldsm_x4(kv0s + 8192 + off, qfl[ks]);
    }
    __syncthreads();
    if (tid == 0) { issue_kv(0, 0); issue_kv(1, 1); }

    const int allones = g_mask_flag;

    float accO[8][4];
    #pragma unroll
    for (int n = 0; n < 8; ++n)
        #pragma unroll
        for (int r = 0; r < 4; ++r) accO[n][r] = 0.f;
    float mrow[2] = {-1e30f, -1e30f};
    float lrow[2] = {0.f, 0.f};

    int phase[2] = {0, 0};
    const int NKV = TT / 64;

    for (int kt = 0; kt < NKV; ++kt) {
        const int buf = kt & 1;
        mbar_wait(sm_u + 8 + buf * 8, phase[buf]);
        phase[buf] ^= 1;

        const uint32_t base = kv0s + buf * A_STG;
        const uint32_t tKh = base;
        const uint32_t tKl = base + A_KT;
        const uint32_t tVh = base + 2 * A_KT;
        const uint32_t tVl = base + 3 * A_KT;

        float s[8][4];
        #pragma unroll
        for (int n = 0; n < 8; ++n)
            #pragma unroll
            for (int r = 0; r < 4; ++r) s[n][r] = 0.f;

        #pragma unroll
        for (int ks = 0; ks < 4; ++ks) {
            uint32_t kh[8][2], kl[8][2];
            #pragma unroll
            for (int n2 = 0; n2 < 4; ++n2) {
                int r = n2 * 16 + lr;
                uint32_t off = (uint32_t)r * 128 + (((lc + 2 * ks) ^ (r & 7)) << 4);
                uint32_t th[4], tl[4];
                ldsm_x4(tKh + off, th);
                ldsm_x4(tKl + off, tl);
                kh[n2*2+0][0] = th[0]; kh[n2*2+0][1] = th[2];
                kh[n2*2+1][0] = th[1]; kh[n2*2+1][1] = th[3];
                kl[n2*2+0][0] = tl[0]; kl[n2*2+0][1] = tl[2];
                kl[n2*2+1][0] = tl[1]; kl[n2*2+1][1] = tl[3];
            }
            #pragma unroll
            for (int nj = 0; nj < 8; ++nj)
                mma_bf16(s[nj], qfh[ks], kh[nj][0], kh[nj][1]);
            #pragma unroll
            for (int nj = 0; nj < 8; ++nj)
                mma_bf16(s[nj], qfh[ks], kl[nj][0], kl[nj][1]);
            #pragma unroll
            for (int nj = 0; nj < 8; ++nj)
                mma_bf16(s[nj], qfl[ks], kh[nj][0], kh[nj][1]);
        }

        if (!allones) {
            const int kvb = kt * 64;
            int qrow = q0 + wid * 16 + r0;
            #pragma unroll
            for (int nj = 0; nj < 8; ++nj) {
                int c = kvb + nj * 8 + (lane & 3) * 2;
                const int* m0 = mask + (size_t)qrow * TT + c;
                const int* m1 = mask + (size_t)(qrow + 8) * TT + c;
                if (m0[0] == 0) s[nj][0] = -1e30f;
                if (m0[1] == 0) s[nj][1] = -1e30f;
                if (m1[0] == 0) s[nj][2] = -1e30f;
                if (m1[1] == 0) s[nj][3] = -1e30f;
            }
        }

        float rm0 = -1e30f, rm1 = -1e30f;
        #pragma unroll
        for (int nj = 0; nj < 8; ++nj) {
            rm0 = fmaxf(rm0, fmaxf(s[nj][0], s[nj][1]));
            rm1 = fmaxf(rm1, fmaxf(s[nj][2], s[nj][3]));
        }
        rm0 = fmaxf(rm0, __shfl_xor_sync(0xffffffffu, rm0, 1));
        rm0 = fmaxf(rm0, __shfl_xor_sync(0xffffffffu, rm0, 2));
        rm1 = fmaxf(rm1, __shfl_xor_sync(0xffffffffu, rm1, 1));
        rm1 = fmaxf(rm1, __shfl_xor_sync(0xffffffffu, rm1, 2));

        float mn0 = fmaxf(mrow[0], rm0);
        float mn1 = fmaxf(mrow[1], rm1);
        float c0 = ex2(mrow[0] - mn0);
        float c1 = ex2(mrow[1] - mn1);
        float ps0 = 0.f, ps1 = 0.f;
        #pragma unroll
        for (int nj = 0; nj < 8; ++nj) {
            s[nj][0] = ex2(s[nj][0] - mn0);
            s[nj][1] = ex2(s[nj][1] - mn0);
            s[nj][2] = ex2(s[nj][2] - mn1);
            s[nj][3] = ex2(s[nj][3] - mn1);
            ps0 += s[nj][0] + s[nj][1];
            ps1 += s[nj][2] + s[nj][3];
        }
        ps0 += __shfl_xor_sync(0xffffffffu, ps0, 1);
        ps0 += __shfl_xor_sync(0xffffffffu, ps0, 2);
        ps1 += __shfl_xor_sync(0xffffffffu, ps1, 1);
        ps1 += __shfl_xor_sync(0xffffffffu, ps1, 2);
        lrow[0] = lrow[0] * c0 + ps0;
        lrow[1] = lrow[1] * c1 + ps1;
        mrow[0] = mn0; mrow[1] = mn1;
        #pragma unroll
        for (int nj = 0; nj < 8; ++nj) {
            accO[nj][0] *= c0; accO[nj][1] *= c0;
            accO[nj][2] *= c1; accO[nj][3] *= c1;
        }

        #pragma unroll
        for (int ks = 0; ks < 4; ++ks) {
            uint32_t pfh[4], pfl[4];
            {
                float ra, rb2;
                pfh[0] = pack_hi2(s[2*ks][0],   s[2*ks][1],   ra, rb2);
                pfl[0] = pack_bf2(ra, rb2);
                pfh[1] = pack_hi2(s[2*ks][2],   s[2*ks][3],   ra, rb2);
                pfl[1] = pack_bf2(ra, rb2);
                pfh[2] = pack_hi2(s[2*ks+1][0], s[2*ks+1][1], ra, rb2);
                pfl[2] = pack_bf2(ra, rb2);
                pfh[3] = pack_hi2(s[2*ks+1][2], s[2*ks+1][3], ra, rb2);
                pfl[3] = pack_bf2(ra, rb2);
            }
            uint32_t vh[4][4], vl[4][4];
            #pragma unroll
            for (int g = 0; g < 4; ++g) {
                int r = ks * 16 + lr;
                uint32_t off = (uint32_t)r * 128 + (((lc + 2 * g) ^ (r & 7)) << 4);
                ldsm_x4_t(tVh + off, vh[g]);
                ldsm_x4_t(tVl + off, vl[g]);
            }
            #pragma unroll
            for (int g = 0; g < 4; ++g) {
                mma_bf16(accO[2*g],   pfh, vh[g][0], vh[g][1]);
                mma_bf16(accO[2*g+1], pfh, vh[g][2], vh[g][3]);
            }
            #pragma unroll
            for (int g = 0; g < 4; ++g) {
                mma_bf16(accO[2*g],   pfh, vl[g][0], vl[g][1]);
                mma_bf16(accO[2*g+1], pfh, vl[g][2], vl[g][3]);
            }
            #pragma unroll
            for (int g = 0; g < 4; ++g) {
                mma_bf16(accO[2*g],   pfl, vh[g][0], vh[g][1]);
                mma_bf16(accO[2*g+1], pfl, vh[g][2], vh[g][3]);
            }
        }
        __syncthreads();
        if (tid == 0 && kt + 2 < NKV) issue_kv(kt + 2, buf);
    }

    // ---- epilogue: y packed [rb][ch=h][r][64] SW128 ----
    float inv0 = 1.f / lrow[0];
    float inv1 = 1.f / lrow[1];
    int gr_a = b * TT + q0 + wid * 16 + r0;
    int gr_b = gr_a + 8;
    #pragma unroll
    for (int nj = 0; nj < 8; ++nj) {
        int kin = nj * 8 + (lane & 3) * 2;
        float ra, rb2;
        uint32_t hi2, lo2;
        {
            int rb = gr_a >> 7, r = gr_a & 127;
            size_t row_byte = ((size_t)((rb * 16 + h) * 128 + r)) * 128 + swz128(r, kin);
            hi2 = pack_hi2(accO[nj][0] * inv0, accO[nj][1] * inv0, ra, rb2);
            lo2 = pack_bf2(ra, rb2);
            *reinterpret_cast<uint32_t*>(reinterpret_cast<char*>(yh) + row_byte) = hi2;
            *reinterpret_cast<uint32_t*>(reinterpret_cast<char*>(yl) + row_byte) = lo2;
        }
        {
            int rb = gr_b >> 7, r = gr_b & 127;
            size_t row_byte = ((size_t)((rb * 16 + h) * 128 + r)) * 128 + swz128(r, kin);
            hi2 = pack_hi2(accO[nj][2] * inv1, accO[nj][3] * inv1, ra, rb2);
            lo2 = pack_bf2(ra, rb2);
            *reinterpret_cast<uint32_t*>(reinterpret_cast<char*>(yh) + row_byte) = hi2;
            *reinterpret_cast<uint32_t*>(reinterpret_cast<char*>(yl) + row_byte) = lo2;
        }
    }
}

// ---------------------------------------------------------------------------
extern "C" void kernel_launch(void* const* d_in, const int* in_sizes, int n_in,
                              void* d_out, int out_size)
{
    const float* x     = (const float*)d_in[0];
    const int*   mask  = (const int*)d_in[1];
    const float* w_qkv = (const float*)d_in[2];
    const float* b_qkv = (const float*)d_in[3];
    const float* w_out = (const float*)d_in[4];
    const float* b_out = (const float*)d_in[5];
    float* out = (float*)d_out;

    __nv_bfloat16 *xh, *xl, *wqh, *wql, *woh, *wol, *qph, *qpl, *yh, *yl;
    int* ctrs;
    cudaGetSymbolAddress((void**)&xh, g_xp_hi);
    cudaGetSymbolAddress((void**)&xl, g_xp_lo);
    cudaGetSymbolAddress((void**)&wqh, g_wqkvp_hi);
    cudaGetSymbolAddress((void**)&wql, g_wqkvp_lo);
    cudaGetSymbolAddress((void**)&woh, g_woutp_hi);
    cudaGetSymbolAddress((void**)&wol, g_woutp_lo);
    cudaGetSymbolAddress((void**)&qph, g_qkvp_hi);
    cudaGetSymbolAddress((void**)&qpl, g_qkvp_lo);
    cudaGetSymbolAddress((void**)&yh, g_yp_hi);
    cudaGetSymbolAddress((void**)&yl, g_yp_lo);
    cudaGetSymbolAddress((void**)&ctrs, g_ctrs);

    cudaFuncSetAttribute(gemm_bulk,
                         cudaFuncAttributeMaxDynamicSharedMemorySize, GEMM_SMEM);
    cudaFuncSetAttribute(attn_bulk,
                         cudaFuncAttributeMaxDynamicSharedMemorySize, ATTN_SMEM);

    // 0) fused prep: splits + mask check + counter reset (one launch)
    prep_all<<<(PREP_TOT + 255) / 256, 256>>>(
        x, w_qkv, w_out, mask, xh, xl, wqh, wql, woh, wol);

    // 1) QKV projection (persistent GEMM): tiles = 24 x 64 = 1536
    gemm_bulk<<<2 * NSM, 128, GEMM_SMEM>>>(
        xh, xl, wqh, wql, b_qkv, nullptr, qph, qpl,
        3 * DD, DD, 3 * DD / 128, (3 * DD / 128) * (MM / 64), ctrs + 0);

    // 2) attention (grid-launched, R11): 64-query CTAs, 3 CTAs/SM
    attn_bulk<<<dim3(TT / 64, BB * HH), 128, ATTN_SMEM>>>(
        qph, qpl, mask, yh, yl);

    // 3) output projection (persistent GEMM): tiles = 8 x 64 = 512
    gemm_bulk<<<2 * NSM, 128, GEMM_SMEM>>>(
        yh, yl, woh, wol, b_out, out, nullptr, nullptr,
        DD, DD, DD / 128, (DD / 128) * (MM / 64), ctrs + 2);
}

// round 14
// speedup vs baseline: 1.4677x; 1.4174x over previous
#include <cuda_runtime.h>
#include <cuda_fp16.h>
#include <cstdint>
#include <cstddef>

#define BB 2
#define TT 2048
#define DD 1024
#define HH 16
#define HD 64
#define MM (BB*TT)
#define NSM 148

// ---------------- packed, pre-swizzled fp16 scratch (allocation-free) ----------------
__device__ __half g_xp_hi[(size_t)MM * DD];
__device__ __half g_wqkvp_hi[(size_t)3 * DD * DD];
__device__ __half g_wqkvp_lo[(size_t)3 * DD * DD];
__device__ __half g_woutp_hi[(size_t)DD * DD];
__device__ __half g_woutp_lo[(size_t)DD * DD];
__device__ __half g_qkvp_hi[(size_t)3 * MM * DD];
__device__ __half g_qkvp_lo[(size_t)3 * MM * DD];
__device__ __half g_yp_hi[(size_t)MM * DD];
__device__ int g_mask_flag = 1;
__device__ int g_ctrs[4];

// ---------------- base-target PTX helpers ----------------
__device__ __forceinline__ uint32_t smem_u32(const void* p) {
    uint32_t a;
    asm("{ .reg .u64 t; cvta.to.shared.u64 t, %1; cvt.u32.u64 %0, t; }"
        : "=r"(a) : "l"(p));
    return a;
}
__device__ __forceinline__ void mbar_init(uint32_t mbar, uint32_t cnt) {
    asm volatile("mbarrier.init.shared.b64 [%0], %1;" :: "r"(mbar), "r"(cnt) : "memory");
}
__device__ __forceinline__ void mbar_expect_tx(uint32_t mbar, uint32_t bytes) {
    asm volatile("mbarrier.arrive.expect_tx.shared.b64 _, [%0], %1;"
                 :: "r"(mbar), "r"(bytes) : "memory");
}
__device__ __forceinline__ void mbar_wait(uint32_t mbar, uint32_t parity) {
    asm volatile(
        "{\n\t.reg .pred P;\n\t"
        "WL_%=:\n\t"
        "mbarrier.try_wait.parity.acquire.cta.shared::cta.b64 P, [%0], %1, 0x989680;\n\t"
        "@P bra WD_%=;\n\t"
        "bra WL_%=;\n\t"
        "WD_%=:\n\t}"
        :: "r"(mbar), "r"(parity) : "memory");
}
__device__ __forceinline__ void bulk_g2s(uint32_t dst, const void* src,
                                         uint32_t bytes, uint32_t mbar) {
    asm volatile(
        "cp.async.bulk.shared::cluster.global.mbarrier::complete_tx::bytes "
        "[%0], [%1], %2, [%3];"
        :: "r"(dst), "l"(src), "r"(bytes), "r"(mbar) : "memory");
}
__device__ __forceinline__ void ldsm_x4(uint32_t addr, uint32_t r[4]) {
    asm volatile("ldmatrix.sync.aligned.m8n8.x4.shared.b16 {%0,%1,%2,%3}, [%4];"
                 : "=r"(r[0]), "=r"(r[1]), "=r"(r[2]), "=r"(r[3]) : "r"(addr));
}
__device__ __forceinline__ void ldsm_x4_t(uint32_t addr, uint32_t r[4]) {
    asm volatile("ldmatrix.sync.aligned.m8n8.x4.trans.shared.b16 {%0,%1,%2,%3}, [%4];"
                 : "=r"(r[0]), "=r"(r[1]), "=r"(r[2]), "=r"(r[3]) : "r"(addr));
}
__device__ __forceinline__ void mma_f16(float d[4], const uint32_t a[4],
                                        uint32_t b0, uint32_t b1) {
    asm volatile(
        "mma.sync.aligned.m16n8k16.row.col.f32.f16.f16.f32 "
        "{%0,%1,%2,%3}, {%4,%5,%6,%7}, {%8,%9}, {%0,%1,%2,%3};"
        : "+f"(d[0]), "+f"(d[1]), "+f"(d[2]), "+f"(d[3])
        : "r"(a[0]), "r"(a[1]), "r"(a[2]), "r"(a[3]), "r"(b0), "r"(b1));
}
__device__ __forceinline__ float ex2(float x) {
    float y;
    asm("ex2.approx.f32 %0, %1;" : "=f"(y) : "f"(x));
    return y;
}
__device__ __forceinline__ uint32_t pack_f16x2(float a, float b) {
    __half2 h = __floats2half2_rn(a, b);
    return *reinterpret_cast<uint32_t*>(&h);
}
__device__ __forceinline__ uint32_t pack_f16x2_res(float a, float b,
                                                   float& ra, float& rb) {
    __half2 h = __floats2half2_rn(a, b);
    ra = a - __half2float(__low2half(h));
    rb = b - __half2float(__high2half(h));
    return *reinterpret_cast<uint32_t*>(&h);
}
__device__ __forceinline__ uint32_t swz128(int r, int kin) {
    return (uint32_t)(((((kin >> 3) ^ (r & 7)) << 4)) | ((kin & 7) << 1));
}

// ---------------------------------------------------------------------------
// FUSED prep: x -> hi only; weights -> hi/lo; mask check; counter reset.
// All K=1024 (256 float4 groups per row).
// ---------------------------------------------------------------------------
#define N4X  (MM * DD / 4)
#define N4WQ (3 * DD * DD / 4)
#define N4WO (DD * DD / 4)
#define N4M  (TT * TT / 4)
#define PREP_TOT (N4X + N4WQ + N4WO + N4M)

__device__ __forceinline__ size_t pk_off(int t, int k, int rpb_shift) {
    int rb = t >> rpb_shift;
    int r  = t & ((1 << rpb_shift) - 1);
    int ch = k >> 6;
    int kin = k & 63;
    return ((size_t)((rb * 16 + ch) << rpb_shift) + r) * 128 + swz128(r, kin);
}

__device__ __forceinline__ void do_split_hl(
    const float* __restrict__ src, __half* __restrict__ hi,
    __half* __restrict__ lo, int j, int rpb_shift)
{
    int t = j >> 8;
    int k = (j & 255) << 2;
    float4 v = reinterpret_cast<const float4*>(src)[j];
    float r0, r1, r2, r3;
    uint32_t h01 = pack_f16x2_res(v.x, v.y, r0, r1);
    uint32_t h23 = pack_f16x2_res(v.z, v.w, r2, r3);
    uint32_t l01 = pack_f16x2(r0, r1);
    uint32_t l23 = pack_f16x2(r2, r3);
    size_t off = pk_off(t, k, rpb_shift);
    uint2 hv; hv.x = h01; hv.y = h23;
    uint2 lv; lv.x = l01; lv.y = l23;
    *reinterpret_cast<uint2*>(reinterpret_cast<char*>(hi) + off) = hv;
    *reinterpret_cast<uint2*>(reinterpret_cast<char*>(lo) + off) = lv;
}

__device__ __forceinline__ void do_split_h(
    const float* __restrict__ src, __half* __restrict__ hi, int j, int rpb_shift)
{
    int t = j >> 8;
    int k = (j & 255) << 2;
    float4 v = reinterpret_cast<const float4*>(src)[j];
    uint2 hv;
    hv.x = pack_f16x2(v.x, v.y);
    hv.y = pack_f16x2(v.z, v.w);
    *reinterpret_cast<uint2*>(reinterpret_cast<char*>(hi) + pk_off(t, k, rpb_shift)) = hv;
}

__global__ void __launch_bounds__(256) prep_all(
    const float* __restrict__ x, const float* __restrict__ wqkv,
    const float* __restrict__ wout, const int* __restrict__ mask,
    __half* __restrict__ xh,
    __half* __restrict__ wqh, __half* __restrict__ wql,
    __half* __restrict__ woh, __half* __restrict__ wol)
{
    int i = blockIdx.x * 256 + threadIdx.x;
    if (blockIdx.x == 0 && threadIdx.x < 4) g_ctrs[threadIdx.x] = 0;
    if (i < N4X) {
        do_split_h(x, xh, i, 7);
    } else if (i < N4X + N4WQ) {
        do_split_hl(wqkv, wqh, wql, i - N4X, 8);
    } else if (i < N4X + N4WQ + N4WO) {
        do_split_hl(wout, woh, wol, i - N4X - N4WQ, 8);
    } else if (i < PREP_TOT) {
        int4 v = reinterpret_cast<const int4*>(mask)[i - N4X - N4WQ - N4WO];
        if (v.x == 0 || v.y == 0 || v.z == 0 || v.w == 0) g_mask_flag = 0;
    }
}

// ---------------------------------------------------------------------------
// PERSISTENT 2-pass fp16 GEMM: C = Ah·(Bh+Bl)^T + bias.
// 128 threads (2x2 warps), tile 64x128, BK=64, 2-stage bulk, 2 CTAs/SM.
// ---------------------------------------------------------------------------
#define G_AT 8192
#define G_BT 16384
#define G_STG (G_AT + 2*G_BT)          // 40960
#define G_HDR 128
#define GEMM_SMEM (G_HDR + 2*G_STG)    // 82048

__global__ void __launch_bounds__(128, 2)
gemm_bulk(const __half* __restrict__ Ahp,
          const __half* __restrict__ Bhp, const __half* __restrict__ Blp,
          const float* __restrict__ bias, float* __restrict__ C,
          __half* __restrict__ Qhi, __half* __restrict__ Qlo,
          int N, int K, int gx, int total, int* __restrict__ ctr)
{
    extern __shared__ __align__(128) char sm[];
    const uint32_t sm_u = smem_u32(sm);
    const uint32_t stg0 = sm_u + G_HDR;

    const int tid  = threadIdx.x;
    const int lane = tid & 31;
    const int wid  = tid >> 5;
    const int wm   = wid & 1;
    const int wn   = wid >> 1;
    const int nch  = K >> 6;
    const int lr = lane & 15;
    const int lc = lane >> 4;

    if (tid == 0) { mbar_init(sm_u, 1); mbar_init(sm_u + 8, 1); }
    __syncthreads();

    __shared__ int s_tile;
    int phase[2] = {0, 0};

    for (;;) {
        if (tid == 0) s_tile = atomicAdd(ctr, 1);
        __syncthreads();
        const int tt = s_tile;
        if (tt >= total) break;
        const int row0 = (tt / gx) * 64;
        const int col0 = (tt % gx) * 128;

        const int rbA = row0 >> 7;
        const int ra0 = row0 & 127;
        const int nbB = col0 >> 8;
        const int cb0 = col0 & 255;

        auto issue = [&](int ch, int bufi) {
            const uint32_t base = stg0 + bufi * G_STG;
            const uint32_t mb = sm_u + bufi * 8;
            mbar_expect_tx(mb, G_STG);
            size_t ea = ((size_t)(((rbA * nch + ch) << 7) + ra0)) << 6;
            size_t eb = ((size_t)(((nbB * nch + ch) << 8) + cb0)) << 6;
            bulk_g2s(base,            Ahp + ea, G_AT, mb);
            bulk_g2s(base + G_AT,     Bhp + eb, G_BT, mb);
            bulk_g2s(base + G_AT+G_BT,Blp + eb, G_BT, mb);
        };

        float acc[2][8][4];
        #pragma unroll
        for (int i = 0; i < 2; ++i)
            #pragma unroll
            for (int j = 0; j < 8; ++j)
                #pragma unroll
                for (int r = 0; r < 4; ++r) acc[i][j][r] = 0.f;

        if (tid == 0) { issue(0, 0); issue(1, 1); }

        for (int ch = 0; ch < nch; ++ch) {
            const int buf = ch & 1;
            mbar_wait(sm_u + buf * 8, phase[buf]);
            phase[buf] ^= 1;

            const uint32_t base = stg0 + buf * G_STG;
            const uint32_t tAh = base;
            const uint32_t tBh = base + G_AT;
            const uint32_t tBl = base + G_AT + G_BT;

            #pragma unroll
            for (int kk8 = 0; kk8 < 8; kk8 += 2) {
                uint32_t ah[2][4];
                uint32_t bh[8][2], bl[8][2];
                #pragma unroll
                for (int mi = 0; mi < 2; ++mi) {
                    int r = wm * 32 + mi * 16 + lr;
                    uint32_t off = (uint32_t)r * 128 + ((((lc + kk8) ^ (r & 7))) << 4);
                    ldsm_x4(tAh + off, ah[mi]);
                }
                #pragma unroll
                for (int n2 = 0; n2 < 4; ++n2) {
                    int r = wn * 64 + n2 * 16 + lr;
                    uint32_t off = (uint32_t)r * 128 + ((((lc + kk8) ^ (r & 7))) << 4);
                    uint32_t th[4], tl[4];
                    ldsm_x4(tBh + off, th);
                    ldsm_x4(tBl + off, tl);
                    bh[n2*2+0][0] = th[0]; bh[n2*2+0][1] = th[2];
                    bh[n2*2+1][0] = th[1]; bh[n2*2+1][1] = th[3];
                    bl[n2*2+0][0] = tl[0]; bl[n2*2+0][1] = tl[2];
                    bl[n2*2+1][0] = tl[1]; bl[n2*2+1][1] = tl[3];
                }
                #pragma unroll
                for (int mi = 0; mi < 2; ++mi)
                    #pragma unroll
                    for (int nj = 0; nj < 8; ++nj)
                        mma_f16(acc[mi][nj], ah[mi], bh[nj][0], bh[nj][1]);
                #pragma unroll
                for (int mi = 0; mi < 2; ++mi)
                    #pragma unroll
                    for (int nj = 0; nj < 8; ++nj)
                        mma_f16(acc[mi][nj], ah[mi], bl[nj][0], bl[nj][1]);
            }
            __syncthreads();
            if (tid == 0 && ch + 2 < nch) issue(ch + 2, buf);
        }

        // ---- epilogue ----
        #pragma unroll
        for (int mi = 0; mi < 2; ++mi) {
            #pragma unroll
            for (int nj = 0; nj < 8; ++nj) {
                int col = col0 + wn * 64 + nj * 8 + (lane & 3) * 2;
                float b0 = bias[col], b1 = bias[col + 1];
                #pragma unroll
                for (int hh2 = 0; hh2 < 2; ++hh2) {
                    int row = row0 + wm * 32 + mi * 16 + (lane >> 2) + hh2 * 8;
                    float o0 = acc[mi][nj][hh2 * 2 + 0] + b0;
                    float o1 = acc[mi][nj][hh2 * 2 + 1] + b1;
                    if (Qhi) {
                        int comp = col >> 10;
                        float sc = (comp == 0) ? 0.18033688011112042f : 1.0f;
                        o0 *= sc; o1 *= sc;
                        int hd = (col >> 6) & 15;
                        int d  = col & 63;
                        int bg = row >> 11;
                        int t2 = row & 2047;
                        size_t row_byte =
                            ((size_t)(((comp * 2 + bg) * 16 + hd) * 2048 + t2)) * 128
                            + swz128(t2, d);
                        float r0, r1;
                        uint32_t hi2 = pack_f16x2_res(o0, o1, r0, r1);
                        uint32_t lo2 = pack_f16x2(r0, r1);
                        *reinterpret_cast<uint32_t*>(reinterpret_cast<char*>(Qhi) + row_byte) = hi2;
                        *reinterpret_cast<uint32_t*>(reinterpret_cast<char*>(Qlo) + row_byte) = lo2;
                    } else {
                        float2 o; o.x = o0; o.y = o1;
                        *reinterpret_cast<float2*>(C + (size_t)row * N + col) = o;
                    }
                }
            }
        }
    }
}

// ---------------------------------------------------------------------------
// Flash attention (2-pass fp16): grid-launched, 128 threads, q-tile 64,
// 3 CTAs/SM. S = Qh·(Kh+Kl); O = Ph·(Vh+Vl). Q/P need no residual.
// Log2-domain softmax (Q pre-scaled), ex2. Output y hi only.
// ---------------------------------------------------------------------------
#define A_KT 8192
#define A_STG (4 * A_KT)
#define A_HDR 128
#define ATTN_SMEM (A_HDR + 2 * A_STG)

__global__ void __launch_bounds__(128, 3)
attn_bulk(const __half* __restrict__ qph, const __half* __restrict__ qpl,
          const int* __restrict__ mask, __half* __restrict__ yh)
{
    extern __shared__ __align__(128) char sm[];
    const uint32_t sm_u = smem_u32(sm);
    const uint32_t kv0s = sm_u + A_HDR;

    const int tid  = threadIdx.x;
    const int lane = tid & 31;
    const int wid  = tid >> 5;
    const int q0   = blockIdx.x * 64;
    const int b    = blockIdx.y >> 4;
    const int h    = blockIdx.y & 15;
    const int lr = lane & 15;
    const int lc = lane >> 4;
    const int r0 = lane >> 2;

    const size_t CS = (size_t)2 * 16 * 2048 * 64;
    const size_t bh_base = ((size_t)(b * 16 + h) * 2048) * 64;

    if (tid == 0) {
        mbar_init(sm_u, 1);
        mbar_init(sm_u + 8, 1);
        mbar_init(sm_u + 16, 1);
    }
    __syncthreads();

    auto issue_kv = [&](int kt, int bufi) {
        const uint32_t mb = sm_u + 8 + bufi * 8;
        const uint32_t base = kv0s + bufi * A_STG;
        const size_t koff = bh_base + (size_t)(kt * 64) * 64;
        mbar_expect_tx(mb, A_STG);
        bulk_g2s(base,            qph + CS + koff,     A_KT, mb);   // Kh
        bulk_g2s(base + A_KT,     qpl + CS + koff,     A_KT, mb);   // Kl
        bulk_g2s(base + 2*A_KT,   qph + 2*CS + koff,   A_KT, mb);   // Vh
        bulk_g2s(base + 3*A_KT,   qpl + 2*CS + koff,   A_KT, mb);   // Vl
    };

    // ---- stage Q (hi only) in kv buffer 0, load fragments, free it ----
    if (tid == 0) {
        mbar_expect_tx(sm_u, 8192);
        bulk_g2s(kv0s, qph + bh_base + (size_t)q0 * 64, 8192, sm_u);
    }
    mbar_wait(sm_u, 0);
    uint32_t qfh[4][4];
    #pragma unroll
    for (int ks = 0; ks < 4; ++ks) {
        int r = wid * 16 + lr;
        uint32_t off = (uint32_t)r * 128 + (((lc + 2 * ks) ^ (r & 7)) << 4);
        ldsm_x4(kv0s + off, qfh[ks]);
    }
    __syncthreads();
    if (tid == 0) { issue_kv(0, 0); issue_kv(1, 1); }

    const int allones = g_mask_flag;

    float accO[8][4];
    #pragma unroll
    for (int n = 0; n < 8; ++n)
        #pragma unroll
        for (int r = 0; r < 4; ++r) accO[n][r] = 0.f;
    float mrow[2] = {-1e30f, -1e30f};
    float lrow[2] = {0.f, 0.f};

    int phase[2] = {0, 0};
    const int NKV = TT / 64;

    for (int kt = 0; kt < NKV; ++kt) {
        const int buf = kt & 1;
        mbar_wait(sm_u + 8 + buf * 8, phase[buf]);
        phase[buf] ^= 1;

        const uint32_t base = kv0s + buf * A_STG;
        const uint32_t tKh = base;
        const uint32_t tKl = base + A_KT;
        const uint32_t tVh = base + 2 * A_KT;
        const uint32_t tVl = base + 3 * A_KT;

        // ---- S = Qh @ (Kh + Kl)^T (2 passes) ----
        float s[8][4];
        #pragma unroll
        for (int n = 0; n < 8; ++n)
            #pragma unroll
            for (int r = 0; r < 4; ++r) s[n][r] = 0.f;

        #pragma unroll
        for (int ks = 0; ks < 4; ++ks) {
            uint32_t kh[8][2], kl[8][2];
            #pragma unroll
            for (int n2 = 0; n2 < 4; ++n2) {
                int r = n2 * 16 + lr;
                uint32_t off = (uint32_t)r * 128 + (((lc + 2 * ks) ^ (r & 7)) << 4);
                uint32_t th[4], tl[4];
                ldsm_x4(tKh + off, th);
                ldsm_x4(tKl + off, tl);
                kh[n2*2+0][0] = th[0]; kh[n2*2+0][1] = th[2];
                kh[n2*2+1][0] = th[1]; kh[n2*2+1][1] = th[3];
                kl[n2*2+0][0] = tl[0]; kl[n2*2+0][1] = tl[2];
                kl[n2*2+1][0] = tl[1]; kl[n2*2+1][1] = tl[3];
            }
            #pragma unroll
            for (int nj = 0; nj < 8; ++nj)
                mma_f16(s[nj], qfh[ks], kh[nj][0], kh[nj][1]);
            #pragma unroll
            for (int nj = 0; nj < 8; ++nj)
                mma_f16(s[nj], qfh[ks], kl[nj][0], kl[nj][1]);
        }

        if (!allones) {
            const int kvb = kt * 64;
            int qrow = q0 + wid * 16 + r0;
            #pragma unroll
            for (int nj = 0; nj < 8; ++nj) {
                int c = kvb + nj * 8 + (lane & 3) * 2;
                const int* m0 = mask + (size_t)qrow * TT + c;
                const int* m1 = mask + (size_t)(qrow + 8) * TT + c;
                if (m0[0] == 0) s[nj][0] = -1e30f;
                if (m0[1] == 0) s[nj][1] = -1e30f;
                if (m1[0] == 0) s[nj][2] = -1e30f;
                if (m1[1] == 0) s[nj][3] = -1e30f;
            }
        }

        // ---- online softmax (log2 domain) ----
        float rm0 = -1e30f, rm1 = -1e30f;
        #pragma unroll
        for (int nj = 0; nj < 8; ++nj) {
            rm0 = fmaxf(rm0, fmaxf(s[nj][0], s[nj][1]));
            rm1 = fmaxf(rm1, fmaxf(s[nj][2], s[nj][3]));
        }
        rm0 = fmaxf(rm0, __shfl_xor_sync(0xffffffffu, rm0, 1));
        rm0 = fmaxf(rm0, __shfl_xor_sync(0xffffffffu, rm0, 2));
        rm1 = fmaxf(rm1, __shfl_xor_sync(0xffffffffu, rm1, 1));
        rm1 = fmaxf(rm1, __shfl_xor_sync(0xffffffffu, rm1, 2));

        float mn0 = fmaxf(mrow[0], rm0);
        float mn1 = fmaxf(mrow[1], rm1);
        float c0 = ex2(mrow[0] - mn0);
        float c1 = ex2(mrow[1] - mn1);
        float ps0 = 0.f, ps1 = 0.f;
        #pragma unroll
        for (int nj = 0; nj < 8; ++nj) {
            s[nj][0] = ex2(s[nj][0] - mn0);
            s[nj][1] = ex2(s[nj][1] - mn0);
            s[nj][2] = ex2(s[nj][2] - mn1);
            s[nj][3] = ex2(s[nj][3] - mn1);
            ps0 += s[nj][0] + s[nj][1];
            ps1 += s[nj][2] + s[nj][3];
        }
        ps0 += __shfl_xor_sync(0xffffffffu, ps0, 1);
        ps0 += __shfl_xor_sync(0xffffffffu, ps0, 2);
        ps1 += __shfl_xor_sync(0xffffffffu, ps1, 1);
        ps1 += __shfl_xor_sync(0xffffffffu, ps1, 2);
        lrow[0] = lrow[0] * c0 + ps0;
        lrow[1] = lrow[1] * c1 + ps1;
        mrow[0] = mn0; mrow[1] = mn1;
        #pragma unroll
        for (int nj = 0; nj < 8; ++nj) {
            accO[nj][0] *= c0; accO[nj][1] *= c0;
            accO[nj][2] *= c1; accO[nj][3] *= c1;
        }

        // ---- O += Ph @ (Vh + Vl) (2 passes; P = plain fp16 cvt) ----
        #pragma unroll
        for (int ks = 0; ks < 4; ++ks) {
            uint32_t pfh[4];
            pfh[0] = pack_f16x2(s[2*ks][0],   s[2*ks][1]);
            pfh[1] = pack_f16x2(s[2*ks][2],   s[2*ks][3]);
            pfh[2] = pack_f16x2(s[2*ks+1][0], s[2*ks+1][1]);
            pfh[3] = pack_f16x2(s[2*ks+1][2], s[2*ks+1][3]);

            uint32_t vh[4][4], vl[4][4];
            #pragma unroll
            for (int g = 0; g < 4; ++g) {
                int r = ks * 16 + lr;
                uint32_t off = (uint32_t)r * 128 + (((lc + 2 * g) ^ (r & 7)) << 4);
                ldsm_x4_t(tVh + off, vh[g]);
                ldsm_x4_t(tVl + off, vl[g]);
            }
            #pragma unroll
            for (int g = 0; g < 4; ++g) {
                mma_f16(accO[2*g],   pfh, vh[g][0], vh[g][1]);
                mma_f16(accO[2*g+1], pfh, vh[g][2], vh[g][3]);
            }
            #pragma unroll
            for (int g = 0; g < 4; ++g) {
                mma_f16(accO[2*g],   pfh, vl[g][0], vl[g][1]);
                mma_f16(accO[2*g+1], pfh, vl[g][2], vl[g][3]);
            }
        }
        __syncthreads();
        if (tid == 0 && kt + 2 < NKV) issue_kv(kt + 2, buf);
    }

    // ---- epilogue: y packed hi only [rb][ch=h][r][64] SW128 ----
    float inv0 = 1.f / lrow[0];
    float inv1 = 1.f / lrow[1];
    int gr_a = b * TT + q0 + wid * 16 + r0;
    int gr_b = gr_a + 8;
    #pragma unroll
    for (int nj = 0; nj < 8; ++nj) {
        int kin = nj * 8 + (lane & 3) * 2;
        {
            int rb = gr_a >> 7, r = gr_a & 127;
            size_t row_byte = ((size_t)((rb * 16 + h) * 128 + r)) * 128 + swz128(r, kin);
            *reinterpret_cast<uint32_t*>(reinterpret_cast<char*>(yh) + row_byte) =
                pack_f16x2(accO[nj][0] * inv0, accO[nj][1] * inv0);
        }
        {
            int rb = gr_b >> 7, r = gr_b & 127;
            size_t row_byte = ((size_t)((rb * 16 + h) * 128 + r)) * 128 + swz128(r, kin);
            *reinterpret_cast<uint32_t*>(reinterpret_cast<char*>(yh) + row_byte) =
                pack_f16x2(accO[nj][2] * inv1, accO[nj][3] * inv1);
        }
    }
}

// ---------------------------------------------------------------------------
extern "C" void kernel_launch(void* const* d_in, const int* in_sizes, int n_in,
                              void* d_out, int out_size)
{
    const float* x     = (const float*)d_in[0];
    const int*   mask  = (const int*)d_in[1];
    const float* w_qkv = (const float*)d_in[2];
    const float* b_qkv = (const float*)d_in[3];
    const float* w_out = (const float*)d_in[4];
    const float* b_out = (const float*)d_in[5];
    float* out = (float*)d_out;

    __half *xh, *wqh, *wql, *woh, *wol, *qph, *qpl, *yh;
    int* ctrs;
    cudaGetSymbolAddress((void**)&xh, g_xp_hi);
    cudaGetSymbolAddress((void**)&wqh, g_wqkvp_hi);
    cudaGetSymbolAddress((void**)&wql, g_wqkvp_lo);
    cudaGetSymbolAddress((void**)&woh, g_woutp_hi);
    cudaGetSymbolAddress((void**)&wol, g_woutp_lo);
    cudaGetSymbolAddress((void**)&qph, g_qkvp_hi);
    cudaGetSymbolAddress((void**)&qpl, g_qkvp_lo);
    cudaGetSymbolAddress((void**)&yh, g_yp_hi);
    cudaGetSymbolAddress((void**)&ctrs, g_ctrs);

    cudaFuncSetAttribute(gemm_bulk,
                         cudaFuncAttributeMaxDynamicSharedMemorySize, GEMM_SMEM);
    cudaFuncSetAttribute(attn_bulk,
                         cudaFuncAttributeMaxDynamicSharedMemorySize, ATTN_SMEM);

    // 0) fused prep
    prep_all<<<(PREP_TOT + 255) / 256, 256>>>(
        x, w_qkv, w_out, mask, xh, wqh, wql, woh, wol);

    // 1) QKV projection (persistent, 2-pass fp16)
    gemm_bulk<<<2 * NSM, 128, GEMM_SMEM>>>(
        xh, wqh, wql, b_qkv, nullptr, qph, qpl,
        3 * DD, DD, 3 * DD / 128, (3 * DD / 128) * (MM / 64), ctrs + 0);

    // 2) attention (grid-launched, 2-pass fp16, 3 CTAs/SM)
    attn_bulk<<<dim3(TT / 64, BB * HH), 128, ATTN_SMEM>>>(
        qph, qpl, mask, yh);

    // 3) output projection (persistent, 2-pass fp16)
    gemm_bulk<<<2 * NSM, 128, GEMM_SMEM>>>(
        yh, woh, wol, b_out, out, nullptr, nullptr,
        DD, DD, DD / 128, (DD / 128) * (MM / 64), ctrs + 2);
}

// round 15
// speedup vs baseline: 1.5995x; 1.0898x over previous
#include <cuda_runtime.h>
#include <cuda_fp16.h>
#include <cstdint>
#include <cstddef>

#define BB 2
#define TT 2048
#define DD 1024
#define HH 16
#define HD 64
#define MM (BB*TT)
#define NSM 148

// ---------------- packed, pre-swizzled fp16 scratch (allocation-free) ----------------
__device__ __half g_xp_hi[(size_t)MM * DD];
__device__ __half g_wqkvp_hi[(size_t)3 * DD * DD];
__device__ __half g_wqkvp_lo[(size_t)3 * DD * DD];
__device__ __half g_woutp_hi[(size_t)DD * DD];
__device__ __half g_woutp_lo[(size_t)DD * DD];
__device__ __half g_qkvp_hi[(size_t)3 * MM * DD];
__device__ __half g_qkvp_lo[(size_t)3 * MM * DD];   // only K-lo is consumed
__device__ __half g_yp_hi[(size_t)MM * DD];
__device__ int g_mask_flag = 1;
__device__ int g_ctrs[4];

// ---------------- base-target PTX helpers ----------------
__device__ __forceinline__ uint32_t smem_u32(const void* p) {
    uint32_t a;
    asm("{ .reg .u64 t; cvta.to.shared.u64 t, %1; cvt.u32.u64 %0, t; }"
        : "=r"(a) : "l"(p));
    return a;
}
__device__ __forceinline__ void mbar_init(uint32_t mbar, uint32_t cnt) {
    asm volatile("mbarrier.init.shared.b64 [%0], %1;" :: "r"(mbar), "r"(cnt) : "memory");
}
__device__ __forceinline__ void mbar_expect_tx(uint32_t mbar, uint32_t bytes) {
    asm volatile("mbarrier.arrive.expect_tx.shared.b64 _, [%0], %1;"
                 :: "r"(mbar), "r"(bytes) : "memory");
}
__device__ __forceinline__ void mbar_wait(uint32_t mbar, uint32_t parity) {
    asm volatile(
        "{\n\t.reg .pred P;\n\t"
        "WL_%=:\n\t"
        "mbarrier.try_wait.parity.acquire.cta.shared::cta.b64 P, [%0], %1, 0x989680;\n\t"
        "@P bra WD_%=;\n\t"
        "bra WL_%=;\n\t"
        "WD_%=:\n\t}"
        :: "r"(mbar), "r"(parity) : "memory");
}
__device__ __forceinline__ void bulk_g2s(uint32_t dst, const void* src,
                                         uint32_t bytes, uint32_t mbar) {
    asm volatile(
        "cp.async.bulk.shared::cluster.global.mbarrier::complete_tx::bytes "
        "[%0], [%1], %2, [%3];"
        :: "r"(dst), "l"(src), "r"(bytes), "r"(mbar) : "memory");
}
__device__ __forceinline__ void ldsm_x4(uint32_t addr, uint32_t r[4]) {
    asm volatile("ldmatrix.sync.aligned.m8n8.x4.shared.b16 {%0,%1,%2,%3}, [%4];"
                 : "=r"(r[0]), "=r"(r[1]), "=r"(r[2]), "=r"(r[3]) : "r"(addr));
}
__device__ __forceinline__ void ldsm_x4_t(uint32_t addr, uint32_t r[4]) {
    asm volatile("ldmatrix.sync.aligned.m8n8.x4.trans.shared.b16 {%0,%1,%2,%3}, [%4];"
                 : "=r"(r[0]), "=r"(r[1]), "=r"(r[2]), "=r"(r[3]) : "r"(addr));
}
__device__ __forceinline__ void mma_f16(float d[4], const uint32_t a[4],
                                        uint32_t b0, uint32_t b1) {
    asm volatile(
        "mma.sync.aligned.m16n8k16.row.col.f32.f16.f16.f32 "
        "{%0,%1,%2,%3}, {%4,%5,%6,%7}, {%8,%9}, {%0,%1,%2,%3};"
        : "+f"(d[0]), "+f"(d[1]), "+f"(d[2]), "+f"(d[3])
        : "r"(a[0]), "r"(a[1]), "r"(a[2]), "r"(a[3]), "r"(b0), "r"(b1));
}
__device__ __forceinline__ float ex2(float x) {
    float y;
    asm("ex2.approx.f32 %0, %1;" : "=f"(y) : "f"(x));
    return y;
}
__device__ __forceinline__ uint32_t pack_f16x2(float a, float b) {
    __half2 h = __floats2half2_rn(a, b);
    return *reinterpret_cast<uint32_t*>(&h);
}
__device__ __forceinline__ uint32_t pack_f16x2_res(float a, float b,
                                                   float& ra, float& rb) {
    __half2 h = __floats2half2_rn(a, b);
    ra = a - __half2float(__low2half(h));
    rb = b - __half2float(__high2half(h));
    return *reinterpret_cast<uint32_t*>(&h);
}
__device__ __forceinline__ uint32_t swz128(int r, int kin) {
    return (uint32_t)(((((kin >> 3) ^ (r & 7)) << 4)) | ((kin & 7) << 1));
}

// ---------------------------------------------------------------------------
// FUSED prep: x -> hi only; weights -> hi/lo; mask check; counter reset.
// ---------------------------------------------------------------------------
#define N4X  (MM * DD / 4)
#define N4WQ (3 * DD * DD / 4)
#define N4WO (DD * DD / 4)
#define N4M  (TT * TT / 4)
#define PREP_TOT (N4X + N4WQ + N4WO + N4M)

__device__ __forceinline__ size_t pk_off(int t, int k, int rpb_shift) {
    int rb = t >> rpb_shift;
    int r  = t & ((1 << rpb_shift) - 1);
    int ch = k >> 6;
    int kin = k & 63;
    return ((size_t)((rb * 16 + ch) << rpb_shift) + r) * 128 + swz128(r, kin);
}

__device__ __forceinline__ void do_split_hl(
    const float* __restrict__ src, __half* __restrict__ hi,
    __half* __restrict__ lo, int j, int rpb_shift)
{
    int t = j >> 8;
    int k = (j & 255) << 2;
    float4 v = reinterpret_cast<const float4*>(src)[j];
    float r0, r1, r2, r3;
    uint32_t h01 = pack_f16x2_res(v.x, v.y, r0, r1);
    uint32_t h23 = pack_f16x2_res(v.z, v.w, r2, r3);
    size_t off = pk_off(t, k, rpb_shift);
    uint2 hv; hv.x = h01; hv.y = h23;
    uint2 lv; lv.x = pack_f16x2(r0, r1); lv.y = pack_f16x2(r2, r3);
    *reinterpret_cast<uint2*>(reinterpret_cast<char*>(hi) + off) = hv;
    *reinterpret_cast<uint2*>(reinterpret_cast<char*>(lo) + off) = lv;
}

__device__ __forceinline__ void do_split_h(
    const float* __restrict__ src, __half* __restrict__ hi, int j, int rpb_shift)
{
    int t = j >> 8;
    int k = (j & 255) << 2;
    float4 v = reinterpret_cast<const float4*>(src)[j];
    uint2 hv;
    hv.x = pack_f16x2(v.x, v.y);
    hv.y = pack_f16x2(v.z, v.w);
    *reinterpret_cast<uint2*>(reinterpret_cast<char*>(hi) + pk_off(t, k, rpb_shift)) = hv;
}

__global__ void __launch_bounds__(256) prep_all(
    const float* __restrict__ x, const float* __restrict__ wqkv,
    const float* __restrict__ wout, const int* __restrict__ mask,
    __half* __restrict__ xh,
    __half* __restrict__ wqh, __half* __restrict__ wql,
    __half* __restrict__ woh, __half* __restrict__ wol)
{
    int i = blockIdx.x * 256 + threadIdx.x;
    if (blockIdx.x == 0 && threadIdx.x < 4) g_ctrs[threadIdx.x] = 0;
    if (i < N4X) {
        do_split_h(x, xh, i, 7);
    } else if (i < N4X + N4WQ) {
        do_split_hl(wqkv, wqh, wql, i - N4X, 8);
    } else if (i < N4X + N4WQ + N4WO) {
        do_split_hl(wout, woh, wol, i - N4X - N4WQ, 8);
    } else if (i < PREP_TOT) {
        int4 v = reinterpret_cast<const int4*>(mask)[i - N4X - N4WQ - N4WO];
        if (v.x == 0 || v.y == 0 || v.z == 0 || v.w == 0) g_mask_flag = 0;
    }
}

// ---------------------------------------------------------------------------
// PERSISTENT 2-pass fp16 GEMM (unchanged from R14).
// ---------------------------------------------------------------------------
#define G_AT 8192
#define G_BT 16384
#define G_STG (G_AT + 2*G_BT)
#define G_HDR 128
#define GEMM_SMEM (G_HDR + 2*G_STG)

__global__ void __launch_bounds__(128, 2)
gemm_bulk(const __half* __restrict__ Ahp,
          const __half* __restrict__ Bhp, const __half* __restrict__ Blp,
          const float* __restrict__ bias, float* __restrict__ C,
          __half* __restrict__ Qhi, __half* __restrict__ Qlo,
          int N, int K, int gx, int total, int* __restrict__ ctr)
{
    extern __shared__ __align__(128) char sm[];
    const uint32_t sm_u = smem_u32(sm);
    const uint32_t stg0 = sm_u + G_HDR;

    const int tid  = threadIdx.x;
    const int lane = tid & 31;
    const int wid  = tid >> 5;
    const int wm   = wid & 1;
    const int wn   = wid >> 1;
    const int nch  = K >> 6;
    const int lr = lane & 15;
    const int lc = lane >> 4;

    if (tid == 0) { mbar_init(sm_u, 1); mbar_init(sm_u + 8, 1); }
    __syncthreads();

    __shared__ int s_tile;
    int phase[2] = {0, 0};

    for (;;) {
        if (tid == 0) s_tile = atomicAdd(ctr, 1);
        __syncthreads();
        const int tt = s_tile;
        if (tt >= total) break;
        const int row0 = (tt / gx) * 64;
        const int col0 = (tt % gx) * 128;

        const int rbA = row0 >> 7;
        const int ra0 = row0 & 127;
        const int nbB = col0 >> 8;
        const int cb0 = col0 & 255;

        auto issue = [&](int ch, int bufi) {
            const uint32_t base = stg0 + bufi * G_STG;
            const uint32_t mb = sm_u + bufi * 8;
            mbar_expect_tx(mb, G_STG);
            size_t ea = ((size_t)(((rbA * nch + ch) << 7) + ra0)) << 6;
            size_t eb = ((size_t)(((nbB * nch + ch) << 8) + cb0)) << 6;
            bulk_g2s(base,            Ahp + ea, G_AT, mb);
            bulk_g2s(base + G_AT,     Bhp + eb, G_BT, mb);
            bulk_g2s(base + G_AT+G_BT,Blp + eb, G_BT, mb);
        };

        float acc[2][8][4];
        #pragma unroll
        for (int i = 0; i < 2; ++i)
            #pragma unroll
            for (int j = 0; j < 8; ++j)
                #pragma unroll
                for (int r = 0; r < 4; ++r) acc[i][j][r] = 0.f;

        if (tid == 0) { issue(0, 0); issue(1, 1); }

        for (int ch = 0; ch < nch; ++ch) {
            const int buf = ch & 1;
            mbar_wait(sm_u + buf * 8, phase[buf]);
            phase[buf] ^= 1;

            const uint32_t base = stg0 + buf * G_STG;
            const uint32_t tAh = base;
            const uint32_t tBh = base + G_AT;
            const uint32_t tBl = base + G_AT + G_BT;

            #pragma unroll
            for (int kk8 = 0; kk8 < 8; kk8 += 2) {
                uint32_t ah[2][4];
                uint32_t bh[8][2], bl[8][2];
                #pragma unroll
                for (int mi = 0; mi < 2; ++mi) {
                    int r = wm * 32 + mi * 16 + lr;
                    uint32_t off = (uint32_t)r * 128 + ((((lc + kk8) ^ (r & 7))) << 4);
                    ldsm_x4(tAh + off, ah[mi]);
                }
                #pragma unroll
                for (int n2 = 0; n2 < 4; ++n2) {
                    int r = wn * 64 + n2 * 16 + lr;
                    uint32_t off = (uint32_t)r * 128 + ((((lc + kk8) ^ (r & 7))) << 4);
                    uint32_t th[4], tl[4];
                    ldsm_x4(tBh + off, th);
                    ldsm_x4(tBl + off, tl);
                    bh[n2*2+0][0] = th[0]; bh[n2*2+0][1] = th[2];
                    bh[n2*2+1][0] = th[1]; bh[n2*2+1][1] = th[3];
                    bl[n2*2+0][0] = tl[0]; bl[n2*2+0][1] = tl[2];
                    bl[n2*2+1][0] = tl[1]; bl[n2*2+1][1] = tl[3];
                }
                #pragma unroll
                for (int mi = 0; mi < 2; ++mi)
                    #pragma unroll
                    for (int nj = 0; nj < 8; ++nj)
                        mma_f16(acc[mi][nj], ah[mi], bh[nj][0], bh[nj][1]);
                #pragma unroll
                for (int mi = 0; mi < 2; ++mi)
                    #pragma unroll
                    for (int nj = 0; nj < 8; ++nj)
                        mma_f16(acc[mi][nj], ah[mi], bl[nj][0], bl[nj][1]);
            }
            __syncthreads();
            if (tid == 0 && ch + 2 < nch) issue(ch + 2, buf);
        }

        // ---- epilogue ----
        #pragma unroll
        for (int mi = 0; mi < 2; ++mi) {
            #pragma unroll
            for (int nj = 0; nj < 8; ++nj) {
                int col = col0 + wn * 64 + nj * 8 + (lane & 3) * 2;
                float b0 = bias[col], b1 = bias[col + 1];
                #pragma unroll
                for (int hh2 = 0; hh2 < 2; ++hh2) {
                    int row = row0 + wm * 32 + mi * 16 + (lane >> 2) + hh2 * 8;
                    float o0 = acc[mi][nj][hh2 * 2 + 0] + b0;
                    float o1 = acc[mi][nj][hh2 * 2 + 1] + b1;
                    if (Qhi) {
                        int comp = col >> 10;
                        float sc = (comp == 0) ? 0.18033688011112042f : 1.0f;
                        o0 *= sc; o1 *= sc;
                        int hd = (col >> 6) & 15;
                        int d  = col & 63;
                        int bg = row >> 11;
                        int t2 = row & 2047;
                        size_t row_byte =
                            ((size_t)(((comp * 2 + bg) * 16 + hd) * 2048 + t2)) * 128
                            + swz128(t2, d);
                        float r0, r1;
                        uint32_t hi2 = pack_f16x2_res(o0, o1, r0, r1);
                        uint32_t lo2 = pack_f16x2(r0, r1);
                        *reinterpret_cast<uint32_t*>(reinterpret_cast<char*>(Qhi) + row_byte) = hi2;
                        *reinterpret_cast<uint32_t*>(reinterpret_cast<char*>(Qlo) + row_byte) = lo2;
                    } else {
                        float2 o; o.x = o0; o.y = o1;
                        *reinterpret_cast<float2*>(C + (size_t)row * N + col) = o;
                    }
                }
            }
        }
    }
}

// ---------------------------------------------------------------------------
// Flash attention: S = Qh·(Kh+Kl), O = Ph·Vh (single-V, no residual).
// 128 threads, q-tile 64, 3 CTAs/SM. Stage = Kh+Kl+Vh = 24KB.
// ---------------------------------------------------------------------------
#define A_KT 8192
#define A_STG (3 * A_KT)                 // 24576
#define A_HDR 128
#define ATTN_SMEM (A_HDR + 2 * A_STG)    // 49280

__global__ void __launch_bounds__(128, 3)
attn_bulk(const __half* __restrict__ qph, const __half* __restrict__ qpl,
          const int* __restrict__ mask, __half* __restrict__ yh)
{
    extern __shared__ __align__(128) char sm[];
    const uint32_t sm_u = smem_u32(sm);
    const uint32_t kv0s = sm_u + A_HDR;

    const int tid  = threadIdx.x;
    const int lane = tid & 31;
    const int wid  = tid >> 5;
    const int q0   = blockIdx.x * 64;
    const int b    = blockIdx.y >> 4;
    const int h    = blockIdx.y & 15;
    const int lr = lane & 15;
    const int lc = lane >> 4;
    const int r0 = lane >> 2;

    const size_t CS = (size_t)2 * 16 * 2048 * 64;
    const size_t bh_base = ((size_t)(b * 16 + h) * 2048) * 64;

    if (tid == 0) {
        mbar_init(sm_u, 1);
        mbar_init(sm_u + 8, 1);
        mbar_init(sm_u + 16, 1);
    }
    __syncthreads();

    auto issue_kv = [&](int kt, int bufi) {
        const uint32_t mb = sm_u + 8 + bufi * 8;
        const uint32_t base = kv0s + bufi * A_STG;
        const size_t koff = bh_base + (size_t)(kt * 64) * 64;
        mbar_expect_tx(mb, A_STG);
        bulk_g2s(base,            qph + CS + koff,     A_KT, mb);   // Kh
        bulk_g2s(base + A_KT,     qpl + CS + koff,     A_KT, mb);   // Kl
        bulk_g2s(base + 2*A_KT,   qph + 2*CS + koff,   A_KT, mb);   // Vh
    };

    // ---- stage Q (hi only) in kv buffer 0, load fragments, free it ----
    if (tid == 0) {
        mbar_expect_tx(sm_u, 8192);
        bulk_g2s(kv0s, qph + bh_base + (size_t)q0 * 64, 8192, sm_u);
    }
    mbar_wait(sm_u, 0);
    uint32_t qfh[4][4];
    #pragma unroll
    for (int ks = 0; ks < 4; ++ks) {
        int r = wid * 16 + lr;
        uint32_t off = (uint32_t)r * 128 + (((lc + 2 * ks) ^ (r & 7)) << 4);
        ldsm_x4(kv0s + off, qfh[ks]);
    }
    __syncthreads();
    if (tid == 0) { issue_kv(0, 0); issue_kv(1, 1); }

    const int allones = g_mask_flag;

    float accO[8][4];
    #pragma unroll
    for (int n = 0; n < 8; ++n)
        #pragma unroll
        for (int r = 0; r < 4; ++r) accO[n][r] = 0.f;
    float mrow[2] = {-1e30f, -1e30f};
    float lrow[2] = {0.f, 0.f};

    int phase[2] = {0, 0};
    const int NKV = TT / 64;

    for (int kt = 0; kt < NKV; ++kt) {
        const int buf = kt & 1;
        mbar_wait(sm_u + 8 + buf * 8, phase[buf]);
        phase[buf] ^= 1;

        const uint32_t base = kv0s + buf * A_STG;
        const uint32_t tKh = base;
        const uint32_t tKl = base + A_KT;
        const uint32_t tVh = base + 2 * A_KT;

        // ---- S = Qh @ (Kh + Kl)^T (2 passes) ----
        float s[8][4];
        #pragma unroll
        for (int n = 0; n < 8; ++n)
            #pragma unroll
            for (int r = 0; r < 4; ++r) s[n][r] = 0.f;

        #pragma unroll
        for (int ks = 0; ks < 4; ++ks) {
            uint32_t kh[8][2], kl[8][2];
            #pragma unroll
            for (int n2 = 0; n2 < 4; ++n2) {
                int r = n2 * 16 + lr;
                uint32_t off = (uint32_t)r * 128 + (((lc + 2 * ks) ^ (r & 7)) << 4);
                uint32_t th[4], tl[4];
                ldsm_x4(tKh + off, th);
                ldsm_x4(tKl + off, tl);
                kh[n2*2+0][0] = th[0]; kh[n2*2+0][1] = th[2];
                kh[n2*2+1][0] = th[1]; kh[n2*2+1][1] = th[3];
                kl[n2*2+0][0] = tl[0]; kl[n2*2+0][1] = tl[2];
                kl[n2*2+1][0] = tl[1]; kl[n2*2+1][1] = tl[3];
            }
            #pragma unroll
            for (int nj = 0; nj < 8; ++nj)
                mma_f16(s[nj], qfh[ks], kh[nj][0], kh[nj][1]);
            #pragma unroll
            for (int nj = 0; nj < 8; ++nj)
                mma_f16(s[nj], qfh[ks], kl[nj][0], kl[nj][1]);
        }

        if (!allones) {
            const int kvb = kt * 64;
            int qrow = q0 + wid * 16 + r0;
            #pragma unroll
            for (int nj = 0; nj < 8; ++nj) {
                int c = kvb + nj * 8 + (lane & 3) * 2;
                const int* m0 = mask + (size_t)qrow * TT + c;
                const int* m1 = mask + (size_t)(qrow + 8) * TT + c;
                if (m0[0] == 0) s[nj][0] = -1e30f;
                if (m0[1] == 0) s[nj][1] = -1e30f;
                if (m1[0] == 0) s[nj][2] = -1e30f;
                if (m1[1] == 0) s[nj][3] = -1e30f;
            }
        }

        // ---- online softmax (log2 domain) ----
        float rm0 = -1e30f, rm1 = -1e30f;
        #pragma unroll
        for (int nj = 0; nj < 8; ++nj) {
            rm0 = fmaxf(rm0, fmaxf(s[nj][0], s[nj][1]));
            rm1 = fmaxf(rm1, fmaxf(s[nj][2], s[nj][3]));
        }
        rm0 = fmaxf(rm0, __shfl_xor_sync(0xffffffffu, rm0, 1));
        rm0 = fmaxf(rm0, __shfl_xor_sync(0xffffffffu, rm0, 2));
        rm1 = fmaxf(rm1, __shfl_xor_sync(0xffffffffu, rm1, 1));
        rm1 = fmaxf(rm1, __shfl_xor_sync(0xffffffffu, rm1, 2));

        float mn0 = fmaxf(mrow[0], rm0);
        float mn1 = fmaxf(mrow[1], rm1);
        float c0 = ex2(mrow[0] - mn0);
        float c1 = ex2(mrow[1] - mn1);
        float ps0 = 0.f, ps1 = 0.f;
        #pragma unroll
        for (int nj = 0; nj < 8; ++nj) {
            s[nj][0] = ex2(s[nj][0] - mn0);
            s[nj][1] = ex2(s[nj][1] - mn0);
            s[nj][2] = ex2(s[nj][2] - mn1);
            s[nj][3] = ex2(s[nj][3] - mn1);
            ps0 += s[nj][0] + s[nj][1];
            ps1 += s[nj][2] + s[nj][3];
        }
        ps0 += __shfl_xor_sync(0xffffffffu, ps0, 1);
        ps0 += __shfl_xor_sync(0xffffffffu, ps0, 2);
        ps1 += __shfl_xor_sync(0xffffffffu, ps1, 1);
        ps1 += __shfl_xor_sync(0xffffffffu, ps1, 2);
        lrow[0] = lrow[0] * c0 + ps0;
        lrow[1] = lrow[1] * c1 + ps1;
        mrow[0] = mn0; mrow[1] = mn1;
        #pragma unroll
        for (int nj = 0; nj < 8; ++nj) {
            accO[nj][0] *= c0; accO[nj][1] *= c0;
            accO[nj][2] *= c1; accO[nj][3] *= c1;
        }

        // ---- O += Ph @ Vh (single pass) ----
        #pragma unroll
        for (int ks = 0; ks < 4; ++ks) {
            uint32_t pfh[4];
            pfh[0] = pack_f16x2(s[2*ks][0],   s[2*ks][1]);
            pfh[1] = pack_f16x2(s[2*ks][2],   s[2*ks][3]);
            pfh[2] = pack_f16x2(s[2*ks+1][0], s[2*ks+1][1]);
            pfh[3] = pack_f16x2(s[2*ks+1][2], s[2*ks+1][3]);

            uint32_t vh[4][4];
            #pragma unroll
            for (int g = 0; g < 4; ++g) {
                int r = ks * 16 + lr;
                uint32_t off = (uint32_t)r * 128 + (((lc + 2 * g) ^ (r & 7)) << 4);
                ldsm_x4_t(tVh + off, vh[g]);
            }
            #pragma unroll
            for (int g = 0; g < 4; ++g) {
                mma_f16(accO[2*g],   pfh, vh[g][0], vh[g][1]);
                mma_f16(accO[2*g+1], pfh, vh[g][2], vh[g][3]);
            }
        }
        __syncthreads();
        if (tid == 0 && kt + 2 < NKV) issue_kv(kt + 2, buf);
    }

    // ---- epilogue: y packed hi only [rb][ch=h][r][64] SW128 ----
    float inv0 = 1.f / lrow[0];
    float inv1 = 1.f / lrow[1];
    int gr_a = b * TT + q0 + wid * 16 + r0;
    int gr_b = gr_a + 8;
    #pragma unroll
    for (int nj = 0; nj < 8; ++nj) {
        int kin = nj * 8 + (lane & 3) * 2;
        {
            int rb = gr_a >> 7, r = gr_a & 127;
            size_t row_byte = ((size_t)((rb * 16 + h) * 128 + r)) * 128 + swz128(r, kin);
            *reinterpret_cast<uint32_t*>(reinterpret_cast<char*>(yh) + row_byte) =
                pack_f16x2(accO[nj][0] * inv0, accO[nj][1] * inv0);
        }
        {
            int rb = gr_b >> 7, r = gr_b & 127;
            size_t row_byte = ((size_t)((rb * 16 + h) * 128 + r)) * 128 + swz128(r, kin);
            *reinterpret_cast<uint32_t*>(reinterpret_cast<char*>(yh) + row_byte) =
                pack_f16x2(accO[nj][2] * inv1, accO[nj][3] * inv1);
        }
    }
}

// ---------------------------------------------------------------------------
extern "C" void kernel_launch(void* const* d_in, const int* in_sizes, int n_in,
                              void* d_out, int out_size)
{
    const float* x     = (const float*)d_in[0];
    const int*   mask  = (const int*)d_in[1];
    const float* w_qkv = (const float*)d_in[2];
    const float* b_qkv = (const float*)d_in[3];
    const float* w_out = (const float*)d_in[4];
    const float* b_out = (const float*)d_in[5];
    float* out = (float*)d_out;

    __half *xh, *wqh, *wql, *woh, *wol, *qph, *qpl, *yh;
    int* ctrs;
    cudaGetSymbolAddress((void**)&xh, g_xp_hi);
    cudaGetSymbolAddress((void**)&wqh, g_wqkvp_hi);
    cudaGetSymbolAddress((void**)&wql, g_wqkvp_lo);
    cudaGetSymbolAddress((void**)&woh, g_woutp_hi);
    cudaGetSymbolAddress((void**)&wol, g_woutp_lo);
    cudaGetSymbolAddress((void**)&qph, g_qkvp_hi);
    cudaGetSymbolAddress((void**)&qpl, g_qkvp_lo);
    cudaGetSymbolAddress((void**)&yh, g_yp_hi);
    cudaGetSymbolAddress((void**)&ctrs, g_ctrs);

    cudaFuncSetAttribute(gemm_bulk,
                         cudaFuncAttributeMaxDynamicSharedMemorySize, GEMM_SMEM);
    cudaFuncSetAttribute(attn_bulk,
                         cudaFuncAttributeMaxDynamicSharedMemorySize, ATTN_SMEM);

    // 0) fused prep
    prep_all<<<(PREP_TOT + 255) / 256, 256>>>(
        x, w_qkv, w_out, mask, xh, wqh, wql, woh, wol);

    // 1) QKV projection (persistent, 2-pass fp16)
    gemm_bulk<<<2 * NSM, 128, GEMM_SMEM>>>(
        xh, wqh, wql, b_qkv, nullptr, qph, qpl,
        3 * DD, DD, 3 * DD / 128, (3 * DD / 128) * (MM / 64), ctrs + 0);

    // 2) attention (grid-launched, single-V fp16, 3 CTAs/SM)
    attn_bulk<<<dim3(TT / 64, BB * HH), 128, ATTN_SMEM>>>(
        qph, qpl, mask, yh);

    // 3) output projection (persistent, 2-pass fp16)
    gemm_bulk<<<2 * NSM, 128, GEMM_SMEM>>>(
        yh, woh, wol, b_out, out, nullptr, nullptr,
        DD, DD, DD / 128, (DD / 128) * (MM / 64), ctrs + 2);
}

// round 16
// speedup vs baseline: 1.8192x; 1.1374x over previous
#include <cuda_runtime.h>
#include <cuda_fp16.h>
#include <cstdint>
#include <cstddef>

#define BB 2
#define TT 2048
#define DD 1024
#define HH 16
#define HD 64
#define MM (BB*TT)
#define NSM 148

// ---------------- packed, pre-swizzled fp16 scratch (allocation-free) ----------------
__device__ __half g_xp_hi[(size_t)MM * DD];
__device__ __half g_wqkvp_hi[(size_t)3 * DD * DD];
__device__ __half g_wqkvp_lo[(size_t)3 * DD * DD];
__device__ __half g_woutp_hi[(size_t)DD * DD];
__device__ __half g_woutp_lo[(size_t)DD * DD];
__device__ __half g_qkvp_hi[(size_t)3 * MM * DD];
__device__ __half g_yp_hi[(size_t)MM * DD];
__device__ int g_mask_flag = 1;
__device__ int g_ctrs[4];

// ---------------- base-target PTX helpers ----------------
__device__ __forceinline__ uint32_t smem_u32(const void* p) {
    uint32_t a;
    asm("{ .reg .u64 t; cvta.to.shared.u64 t, %1; cvt.u32.u64 %0, t; }"
        : "=r"(a) : "l"(p));
    return a;
}
__device__ __forceinline__ void mbar_init(uint32_t mbar, uint32_t cnt) {
    asm volatile("mbarrier.init.shared.b64 [%0], %1;" :: "r"(mbar), "r"(cnt) : "memory");
}
__device__ __forceinline__ void mbar_expect_tx(uint32_t mbar, uint32_t bytes) {
    asm volatile("mbarrier.arrive.expect_tx.shared.b64 _, [%0], %1;"
                 :: "r"(mbar), "r"(bytes) : "memory");
}
__device__ __forceinline__ void mbar_wait(uint32_t mbar, uint32_t parity) {
    asm volatile(
        "{\n\t.reg .pred P;\n\t"
        "WL_%=:\n\t"
        "mbarrier.try_wait.parity.acquire.cta.shared::cta.b64 P, [%0], %1, 0x989680;\n\t"
        "@P bra WD_%=;\n\t"
        "bra WL_%=;\n\t"
        "WD_%=:\n\t}"
        :: "r"(mbar), "r"(parity) : "memory");
}
__device__ __forceinline__ void bulk_g2s(uint32_t dst, const void* src,
                                         uint32_t bytes, uint32_t mbar) {
    asm volatile(
        "cp.async.bulk.shared::cluster.global.mbarrier::complete_tx::bytes "
        "[%0], [%1], %2, [%3];"
        :: "r"(dst), "l"(src), "r"(bytes), "r"(mbar) : "memory");
}
__device__ __forceinline__ void ldsm_x4(uint32_t addr, uint32_t r[4]) {
    asm volatile("ldmatrix.sync.aligned.m8n8.x4.shared.b16 {%0,%1,%2,%3}, [%4];"
                 : "=r"(r[0]), "=r"(r[1]), "=r"(r[2]), "=r"(r[3]) : "r"(addr));
}
__device__ __forceinline__ void ldsm_x4_t(uint32_t addr, uint32_t r[4]) {
    asm volatile("ldmatrix.sync.aligned.m8n8.x4.trans.shared.b16 {%0,%1,%2,%3}, [%4];"
                 : "=r"(r[0]), "=r"(r[1]), "=r"(r[2]), "=r"(r[3]) : "r"(addr));
}
__device__ __forceinline__ void mma_f16(float d[4], const uint32_t a[4],
                                        uint32_t b0, uint32_t b1) {
    asm volatile(
        "mma.sync.aligned.m16n8k16.row.col.f32.f16.f16.f32 "
        "{%0,%1,%2,%3}, {%4,%5,%6,%7}, {%8,%9}, {%0,%1,%2,%3};"
        : "+f"(d[0]), "+f"(d[1]), "+f"(d[2]), "+f"(d[3])
        : "r"(a[0]), "r"(a[1]), "r"(a[2]), "r"(a[3]), "r"(b0), "r"(b1));
}
__device__ __forceinline__ float ex2(float x) {
    float y;
    asm("ex2.approx.f32 %0, %1;" : "=f"(y) : "f"(x));
    return y;
}
__device__ __forceinline__ uint32_t pack_f16x2(float a, float b) {
    __half2 h = __floats2half2_rn(a, b);
    return *reinterpret_cast<uint32_t*>(&h);
}
__device__ __forceinline__ uint32_t pack_f16x2_res(float a, float b,
                                                   float& ra, float& rb) {
    __half2 h = __floats2half2_rn(a, b);
    ra = a - __half2float(__low2half(h));
    rb = b - __half2float(__high2half(h));
    return *reinterpret_cast<uint32_t*>(&h);
}
__device__ __forceinline__ uint32_t swz128(int r, int kin) {
    return (uint32_t)(((((kin >> 3) ^ (r & 7)) << 4)) | ((kin & 7) << 1));
}

// ---------------------------------------------------------------------------
// FUSED prep: x -> hi only; weights -> hi/lo; mask check; counter reset.
// ---------------------------------------------------------------------------
#define N4X  (MM * DD / 4)
#define N4WQ (3 * DD * DD / 4)
#define N4WO (DD * DD / 4)
#define N4M  (TT * TT / 4)
#define PREP_TOT (N4X + N4WQ + N4WO + N4M)

__device__ __forceinline__ size_t pk_off(int t, int k, int rpb_shift) {
    int rb = t >> rpb_shift;
    int r  = t & ((1 << rpb_shift) - 1);
    int ch = k >> 6;
    int kin = k & 63;
    return ((size_t)((rb * 16 + ch) << rpb_shift) + r) * 128 + swz128(r, kin);
}

__device__ __forceinline__ void do_split_hl(
    const float* __restrict__ src, __half* __restrict__ hi,
    __half* __restrict__ lo, int j, int rpb_shift)
{
    int t = j >> 8;
    int k = (j & 255) << 2;
    float4 v = reinterpret_cast<const float4*>(src)[j];
    float r0, r1, r2, r3;
    uint32_t h01 = pack_f16x2_res(v.x, v.y, r0, r1);
    uint32_t h23 = pack_f16x2_res(v.z, v.w, r2, r3);
    size_t off = pk_off(t, k, rpb_shift);
    uint2 hv; hv.x = h01; hv.y = h23;
    uint2 lv; lv.x = pack_f16x2(r0, r1); lv.y = pack_f16x2(r2, r3);
    *reinterpret_cast<uint2*>(reinterpret_cast<char*>(hi) + off) = hv;
    *reinterpret_cast<uint2*>(reinterpret_cast<char*>(lo) + off) = lv;
}

__device__ __forceinline__ void do_split_h(
    const float* __restrict__ src, __half* __restrict__ hi, int j, int rpb_shift)
{
    int t = j >> 8;
    int k = (j & 255) << 2;
    float4 v = reinterpret_cast<const float4*>(src)[j];
    uint2 hv;
    hv.x = pack_f16x2(v.x, v.y);
    hv.y = pack_f16x2(v.z, v.w);
    *reinterpret_cast<uint2*>(reinterpret_cast<char*>(hi) + pk_off(t, k, rpb_shift)) = hv;
}

__global__ void __launch_bounds__(256) prep_all(
    const float* __restrict__ x, const float* __restrict__ wqkv,
    const float* __restrict__ wout, const int* __restrict__ mask,
    __half* __restrict__ xh,
    __half* __restrict__ wqh, __half* __restrict__ wql,
    __half* __restrict__ woh, __half* __restrict__ wol)
{
    int i = blockIdx.x * 256 + threadIdx.x;
    if (blockIdx.x == 0 && threadIdx.x < 4) g_ctrs[threadIdx.x] = 0;
    if (i < N4X) {
        do_split_h(x, xh, i, 7);
    } else if (i < N4X + N4WQ) {
        do_split_hl(wqkv, wqh, wql, i - N4X, 8);
    } else if (i < N4X + N4WQ + N4WO) {
        do_split_hl(wout, woh, wol, i - N4X - N4WQ, 8);
    } else if (i < PREP_TOT) {
        int4 v = reinterpret_cast<const int4*>(mask)[i - N4X - N4WQ - N4WO];
        if (v.x == 0 || v.y == 0 || v.z == 0 || v.w == 0) g_mask_flag = 0;
    }
}

// ---------------------------------------------------------------------------
// PERSISTENT 2-pass fp16 GEMM. Q-output epilogue now writes hi ONLY.
// ---------------------------------------------------------------------------
#define G_AT 8192
#define G_BT 16384
#define G_STG (G_AT + 2*G_BT)
#define G_HDR 128
#define GEMM_SMEM (G_HDR + 2*G_STG)

__global__ void __launch_bounds__(128, 2)
gemm_bulk(const __half* __restrict__ Ahp,
          const __half* __restrict__ Bhp, const __half* __restrict__ Blp,
          const float* __restrict__ bias, float* __restrict__ C,
          __half* __restrict__ Qhi,
          int N, int K, int gx, int total, int* __restrict__ ctr)
{
    extern __shared__ __align__(128) char sm[];
    const uint32_t sm_u = smem_u32(sm);
    const uint32_t stg0 = sm_u + G_HDR;

    const int tid  = threadIdx.x;
    const int lane = tid & 31;
    const int wid  = tid >> 5;
    const int wm   = wid & 1;
    const int wn   = wid >> 1;
    const int nch  = K >> 6;
    const int lr = lane & 15;
    const int lc = lane >> 4;

    if (tid == 0) { mbar_init(sm_u, 1); mbar_init(sm_u + 8, 1); }
    __syncthreads();

    __shared__ int s_tile;
    int phase[2] = {0, 0};

    for (;;) {
        if (tid == 0) s_tile = atomicAdd(ctr, 1);
        __syncthreads();
        const int tt = s_tile;
        if (tt >= total) break;
        const int row0 = (tt / gx) * 64;
        const int col0 = (tt % gx) * 128;

        const int rbA = row0 >> 7;
        const int ra0 = row0 & 127;
        const int nbB = col0 >> 8;
        const int cb0 = col0 & 255;

        auto issue = [&](int ch, int bufi) {
            const uint32_t base = stg0 + bufi * G_STG;
            const uint32_t mb = sm_u + bufi * 8;
            mbar_expect_tx(mb, G_STG);
            size_t ea = ((size_t)(((rbA * nch + ch) << 7) + ra0)) << 6;
            size_t eb = ((size_t)(((nbB * nch + ch) << 8) + cb0)) << 6;
            bulk_g2s(base,            Ahp + ea, G_AT, mb);
            bulk_g2s(base + G_AT,     Bhp + eb, G_BT, mb);
            bulk_g2s(base + G_AT+G_BT,Blp + eb, G_BT, mb);
        };

        float acc[2][8][4];
        #pragma unroll
        for (int i = 0; i < 2; ++i)
            #pragma unroll
            for (int j = 0; j < 8; ++j)
                #pragma unroll
                for (int r = 0; r < 4; ++r) acc[i][j][r] = 0.f;

        if (tid == 0) { issue(0, 0); issue(1, 1); }

        for (int ch = 0; ch < nch; ++ch) {
            const int buf = ch & 1;
            mbar_wait(sm_u + buf * 8, phase[buf]);
            phase[buf] ^= 1;

            const uint32_t base = stg0 + buf * G_STG;
            const uint32_t tAh = base;
            const uint32_t tBh = base + G_AT;
            const uint32_t tBl = base + G_AT + G_BT;

            #pragma unroll
            for (int kk8 = 0; kk8 < 8; kk8 += 2) {
                uint32_t ah[2][4];
                uint32_t bh[8][2], bl[8][2];
                #pragma unroll
                for (int mi = 0; mi < 2; ++mi) {
                    int r = wm * 32 + mi * 16 + lr;
                    uint32_t off = (uint32_t)r * 128 + ((((lc + kk8) ^ (r & 7))) << 4);
                    ldsm_x4(tAh + off, ah[mi]);
                }
                #pragma unroll
                for (int n2 = 0; n2 < 4; ++n2) {
                    int r = wn * 64 + n2 * 16 + lr;
                    uint32_t off = (uint32_t)r * 128 + ((((lc + kk8) ^ (r & 7))) << 4);
                    uint32_t th[4], tl[4];
                    ldsm_x4(tBh + off, th);
                    ldsm_x4(tBl + off, tl);
                    bh[n2*2+0][0] = th[0]; bh[n2*2+0][1] = th[2];
                    bh[n2*2+1][0] = th[1]; bh[n2*2+1][1] = th[3];
                    bl[n2*2+0][0] = tl[0]; bl[n2*2+0][1] = tl[2];
                    bl[n2*2+1][0] = tl[1]; bl[n2*2+1][1] = tl[3];
                }
                #pragma unroll
                for (int mi = 0; mi < 2; ++mi)
                    #pragma unroll
                    for (int nj = 0; nj < 8; ++nj)
                        mma_f16(acc[mi][nj], ah[mi], bh[nj][0], bh[nj][1]);
                #pragma unroll
                for (int mi = 0; mi < 2; ++mi)
                    #pragma unroll
                    for (int nj = 0; nj < 8; ++nj)
                        mma_f16(acc[mi][nj], ah[mi], bl[nj][0], bl[nj][1]);
            }
            __syncthreads();
            if (tid == 0 && ch + 2 < nch) issue(ch + 2, buf);
        }

        // ---- epilogue ----
        #pragma unroll
        for (int mi = 0; mi < 2; ++mi) {
            #pragma unroll
            for (int nj = 0; nj < 8; ++nj) {
                int col = col0 + wn * 64 + nj * 8 + (lane & 3) * 2;
                float b0 = bias[col], b1 = bias[col + 1];
                #pragma unroll
                for (int hh2 = 0; hh2 < 2; ++hh2) {
                    int row = row0 + wm * 32 + mi * 16 + (lane >> 2) + hh2 * 8;
                    float o0 = acc[mi][nj][hh2 * 2 + 0] + b0;
                    float o1 = acc[mi][nj][hh2 * 2 + 1] + b1;
                    if (Qhi) {
                        int comp = col >> 10;
                        float sc = (comp == 0) ? 0.18033688011112042f : 1.0f;
                        o0 *= sc; o1 *= sc;
                        int hd = (col >> 6) & 15;
                        int d  = col & 63;
                        int bg = row >> 11;
                        int t2 = row & 2047;
                        size_t row_byte =
                            ((size_t)(((comp * 2 + bg) * 16 + hd) * 2048 + t2)) * 128
                            + swz128(t2, d);
                        *reinterpret_cast<uint32_t*>(reinterpret_cast<char*>(Qhi) + row_byte) =
                            pack_f16x2(o0, o1);
                    } else {
                        float2 o; o.x = o0; o.y = o1;
                        *reinterpret_cast<float2*>(C + (size_t)row * N + col) = o;
                    }
                }
            }
        }
    }
}

// ---------------------------------------------------------------------------
// Flash attention, plain fp16 K/V: S = Qh·Kh, O = Ph·Vh.
// 128 threads, q-tile 64, 4 CTAs/SM. Stage = Kh+Vh = 16KB.
// ---------------------------------------------------------------------------
#define A_KT 8192
#define A_STG (2 * A_KT)                 // 16384
#define A_HDR 128
#define ATTN_SMEM (A_HDR + 2 * A_STG)    // 32896

__global__ void __launch_bounds__(128, 4)
attn_bulk(const __half* __restrict__ qph,
          const int* __restrict__ mask, __half* __restrict__ yh)
{
    extern __shared__ __align__(128) char sm[];
    const uint32_t sm_u = smem_u32(sm);
    const uint32_t kv0s = sm_u + A_HDR;

    const int tid  = threadIdx.x;
    const int lane = tid & 31;
    const int wid  = tid >> 5;
    const int q0   = blockIdx.x * 64;
    const int b    = blockIdx.y >> 4;
    const int h    = blockIdx.y & 15;
    const int lr = lane & 15;
    const int lc = lane >> 4;
    const int r0 = lane >> 2;

    const size_t CS = (size_t)2 * 16 * 2048 * 64;
    const size_t bh_base = ((size_t)(b * 16 + h) * 2048) * 64;

    if (tid == 0) {
        mbar_init(sm_u, 1);
        mbar_init(sm_u + 8, 1);
        mbar_init(sm_u + 16, 1);
    }
    __syncthreads();

    auto issue_kv = [&](int kt, int bufi) {
        const uint32_t mb = sm_u + 8 + bufi * 8;
        const uint32_t base = kv0s + bufi * A_STG;
        const size_t koff = bh_base + (size_t)(kt * 64) * 64;
        mbar_expect_tx(mb, A_STG);
        bulk_g2s(base,          qph + CS + koff,     A_KT, mb);   // Kh
        bulk_g2s(base + A_KT,   qph + 2*CS + koff,   A_KT, mb);   // Vh
    };

    // ---- stage Q in kv buffer 0, load fragments, free it ----
    if (tid == 0) {
        mbar_expect_tx(sm_u, 8192);
        bulk_g2s(kv0s, qph + bh_base + (size_t)q0 * 64, 8192, sm_u);
    }
    mbar_wait(sm_u, 0);
    uint32_t qfh[4][4];
    #pragma unroll
    for (int ks = 0; ks < 4; ++ks) {
        int r = wid * 16 + lr;
        uint32_t off = (uint32_t)r * 128 + (((lc + 2 * ks) ^ (r & 7)) << 4);
        ldsm_x4(kv0s + off, qfh[ks]);
    }
    __syncthreads();
    if (tid == 0) { issue_kv(0, 0); issue_kv(1, 1); }

    const int allones = g_mask_flag;

    float accO[8][4];
    #pragma unroll
    for (int n = 0; n < 8; ++n)
        #pragma unroll
        for (int r = 0; r < 4; ++r) accO[n][r] = 0.f;
    float mrow[2] = {-1e30f, -1e30f};
    float lrow[2] = {0.f, 0.f};

    int phase[2] = {0, 0};
    const int NKV = TT / 64;

    for (int kt = 0; kt < NKV; ++kt) {
        const int buf = kt & 1;
        mbar_wait(sm_u + 8 + buf * 8, phase[buf]);
        phase[buf] ^= 1;

        const uint32_t base = kv0s + buf * A_STG;
        const uint32_t tKh = base;
        const uint32_t tVh = base + A_KT;

        // ---- S = Qh @ Kh^T (single pass) ----
        float s[8][4];
        #pragma unroll
        for (int n = 0; n < 8; ++n)
            #pragma unroll
            for (int r = 0; r < 4; ++r) s[n][r] = 0.f;

        #pragma unroll
        for (int ks = 0; ks < 4; ++ks) {
            uint32_t kh[8][2];
            #pragma unroll
            for (int n2 = 0; n2 < 4; ++n2) {
                int r = n2 * 16 + lr;
                uint32_t off = (uint32_t)r * 128 + (((lc + 2 * ks) ^ (r & 7)) << 4);
                uint32_t th[4];
                ldsm_x4(tKh + off, th);
                kh[n2*2+0][0] = th[0]; kh[n2*2+0][1] = th[2];
                kh[n2*2+1][0] = th[1]; kh[n2*2+1][1] = th[3];
            }
            #pragma unroll
            for (int nj = 0; nj < 8; ++nj)
                mma_f16(s[nj], qfh[ks], kh[nj][0], kh[nj][1]);
        }

        if (!allones) {
            const int kvb = kt * 64;
            int qrow = q0 + wid * 16 + r0;
            #pragma unroll
            for (int nj = 0; nj < 8; ++nj) {
                int c = kvb + nj * 8 + (lane & 3) * 2;
                const int* m0 = mask + (size_t)qrow * TT + c;
                const int* m1 = mask + (size_t)(qrow + 8) * TT + c;
                if (m0[0] == 0) s[nj][0] = -1e30f;
                if (m0[1] == 0) s[nj][1] = -1e30f;
                if (m1[0] == 0) s[nj][2] = -1e30f;
                if (m1[1] == 0) s[nj][3] = -1e30f;
            }
        }

        // ---- online softmax (log2 domain) ----
        float rm0 = -1e30f, rm1 = -1e30f;
        #pragma unroll
        for (int nj = 0; nj < 8; ++nj) {
            rm0 = fmaxf(rm0, fmaxf(s[nj][0], s[nj][1]));
            rm1 = fmaxf(rm1, fmaxf(s[nj][2], s[nj][3]));
        }
        rm0 = fmaxf(rm0, __shfl_xor_sync(0xffffffffu, rm0, 1));
        rm0 = fmaxf(rm0, __shfl_xor_sync(0xffffffffu, rm0, 2));
        rm1 = fmaxf(rm1, __shfl_xor_sync(0xffffffffu, rm1, 1));
        rm1 = fmaxf(rm1, __shfl_xor_sync(0xffffffffu, rm1, 2));

        float mn0 = fmaxf(mrow[0], rm0);
        float mn1 = fmaxf(mrow[1], rm1);
        float c0 = ex2(mrow[0] - mn0);
        float c1 = ex2(mrow[1] - mn1);
        float ps0 = 0.f, ps1 = 0.f;
        #pragma unroll
        for (int nj = 0; nj < 8; ++nj) {
            s[nj][0] = ex2(s[nj][0] - mn0);
            s[nj][1] = ex2(s[nj][1] - mn0);
            s[nj][2] = ex2(s[nj][2] - mn1);
            s[nj][3] = ex2(s[nj][3] - mn1);
            ps0 += s[nj][0] + s[nj][1];
            ps1 += s[nj][2] + s[nj][3];
        }
        ps0 += __shfl_xor_sync(0xffffffffu, ps0, 1);
        ps0 += __shfl_xor_sync(0xffffffffu, ps0, 2);
        ps1 += __shfl_xor_sync(0xffffffffu, ps1, 1);
        ps1 += __shfl_xor_sync(0xffffffffu, ps1, 2);
        lrow[0] = lrow[0] * c0 + ps0;
        lrow[1] = lrow[1] * c1 + ps1;
        mrow[0] = mn0; mrow[1] = mn1;
        #pragma unroll
        for (int nj = 0; nj < 8; ++nj) {
            accO[nj][0] *= c0; accO[nj][1] *= c0;
            accO[nj][2] *= c1; accO[nj][3] *= c1;
        }

        // ---- O += Ph @ Vh ----
        #pragma unroll
        for (int ks = 0; ks < 4; ++ks) {
            uint32_t pfh[4];
            pfh[0] = pack_f16x2(s[2*ks][0],   s[2*ks][1]);
            pfh[1] = pack_f16x2(s[2*ks][2],   s[2*ks][3]);
            pfh[2] = pack_f16x2(s[2*ks+1][0], s[2*ks+1][1]);
            pfh[3] = pack_f16x2(s[2*ks+1][2], s[2*ks+1][3]);

            uint32_t vh[4][4];
            #pragma unroll
            for (int g = 0; g < 4; ++g) {
                int r = ks * 16 + lr;
                uint32_t off = (uint32_t)r * 128 + (((lc + 2 * g) ^ (r & 7)) << 4);
                ldsm_x4_t(tVh + off, vh[g]);
            }
            #pragma unroll
            for (int g = 0; g < 4; ++g) {
                mma_f16(accO[2*g],   pfh, vh[g][0], vh[g][1]);
                mma_f16(accO[2*g+1], pfh, vh[g][2], vh[g][3]);
            }
        }
        __syncthreads();
        if (tid == 0 && kt + 2 < NKV) issue_kv(kt + 2, buf);
    }

    // ---- epilogue: y packed hi [rb][ch=h][r][64] SW128 ----
    float inv0 = 1.f / lrow[0];
    float inv1 = 1.f / lrow[1];
    int gr_a = b * TT + q0 + wid * 16 + r0;
    int gr_b = gr_a + 8;
    #pragma unroll
    for (int nj = 0; nj < 8; ++nj) {
        int kin = nj * 8 + (lane & 3) * 2;
        {
            int rb = gr_a >> 7, r = gr_a & 127;
            size_t row_byte = ((size_t)((rb * 16 + h) * 128 + r)) * 128 + swz128(r, kin);
            *reinterpret_cast<uint32_t*>(reinterpret_cast<char*>(yh) + row_byte) =
                pack_f16x2(accO[nj][0] * inv0, accO[nj][1] * inv0);
        }
        {
            int rb = gr_b >> 7, r = gr_b & 127;
            size_t row_byte = ((size_t)((rb * 16 + h) * 128 + r)) * 128 + swz128(r, kin);
            *reinterpret_cast<uint32_t*>(reinterpret_cast<char*>(yh) + row_byte) =
                pack_f16x2(accO[nj][2] * inv1, accO[nj][3] * inv1);
        }
    }
}

// ---------------------------------------------------------------------------
extern "C" void kernel_launch(void* const* d_in, const int* in_sizes, int n_in,
                              void* d_out, int out_size)
{
    const float* x     = (const float*)d_in[0];
    const int*   mask  = (const int*)d_in[1];
    const float* w_qkv = (const float*)d_in[2];
    const float* b_qkv = (const float*)d_in[3];
    const float* w_out = (const float*)d_in[4];
    const float* b_out = (const float*)d_in[5];
    float* out = (float*)d_out;

    __half *xh, *wqh, *wql, *woh, *wol, *qph, *yh;
    int* ctrs;
    cudaGetSymbolAddress((void**)&xh, g_xp_hi);
    cudaGetSymbolAddress((void**)&wqh, g_wqkvp_hi);
    cudaGetSymbolAddress((void**)&wql, g_wqkvp_lo);
    cudaGetSymbolAddress((void**)&woh, g_woutp_hi);
    cudaGetSymbolAddress((void**)&wol, g_woutp_lo);
    cudaGetSymbolAddress((void**)&qph, g_qkvp_hi);
    cudaGetSymbolAddress((void**)&yh, g_yp_hi);
    cudaGetSymbolAddress((void**)&ctrs, g_ctrs);

    cudaFuncSetAttribute(gemm_bulk,
                         cudaFuncAttributeMaxDynamicSharedMemorySize, GEMM_SMEM);
    cudaFuncSetAttribute(attn_bulk,
                         cudaFuncAttributeMaxDynamicSharedMemorySize, ATTN_SMEM);

    // 0) fused prep
    prep_all<<<(PREP_TOT + 255) / 256, 256>>>(
        x, w_qkv, w_out, mask, xh, wqh, wql, woh, wol);

    // 1) QKV projection (persistent, 2-pass fp16; writes qkv hi only)
    gemm_bulk<<<2 * NSM, 128, GEMM_SMEM>>>(
        xh, wqh, wql, b_qkv, nullptr, qph,
        3 * DD, DD, 3 * DD / 128, (3 * DD / 128) * (MM / 64), ctrs + 0);

    // 2) attention (plain fp16 K/V, 4 CTAs/SM)
    attn_bulk<<<dim3(TT / 64, BB * HH), 128, ATTN_SMEM>>>(qph, mask, yh);

    // 3) output projection (persistent, 2-pass fp16)
    gemm_bulk<<<2 * NSM, 128, GEMM_SMEM>>>(
        yh, woh, wol, b_out, out, nullptr,
        DD, DD, DD / 128, (DD / 128) * (MM / 64), ctrs + 2);
}